// round 2
// baseline (speedup 1.0000x reference)
#include <cuda_runtime.h>
#include <cuda_bf16.h>

// ---------------- problem constants ----------------
#define BATCH 256
#define NTOK  4096
#define NS    8
#define DD    64
#define HIDN  128
#define NCH   16              // chunks of N for attention partials
#define JC    (NTOK / NCH)    // 256 tokens per chunk
#define SCALE 0.125f          // D^-0.5
#define EPSA  1e-8f

// ---------------- device scratch ----------------
__device__ float g_k[BATCH * NTOK * DD];        // 268 MB
__device__ float g_v[BATCH * NTOK * DD];        // 268 MB
__device__ float g_slots[BATCH * NS * DD];      // 131072
__device__ float g_prior[BATCH * NS * 2 * DD];  // 262144
__device__ float g_pnum[BATCH * NCH * NS * DD]; // 2,097,152
__device__ float g_pden[BATCH * NCH * NS];      // 32768
__device__ float g_kl[BATCH * NS];              // 2048

// =======================================================================
// Kernel 1: x = LN(inputs), k = x@Wk^T+bk, v = x@Wv^T+bv
// 1 warp processes 4 rows per pass; weights transposed in shared.
// =======================================================================
__global__ __launch_bounds__(256) void kv_kernel(
    const float* __restrict__ inputs,
    const float* __restrict__ ni_g, const float* __restrict__ ni_b,
    const float* __restrict__ Wk, const float* __restrict__ bk,
    const float* __restrict__ Wv, const float* __restrict__ bv)
{
    __shared__ __align__(16) float Ws[64 * 132];   // [d][128 outs] padded
    __shared__ __align__(16) float bs[128];
    __shared__ float gs[64], bbeta[64];
    __shared__ float xs[8][4][64];

    int t = threadIdx.x;
    for (int idx = t; idx < 4096; idx += 256) {
        int o = idx >> 6, d = idx & 63;
        Ws[d * 132 + o]      = Wk[idx];   // Wk[o][d]
        Ws[d * 132 + 64 + o] = Wv[idx];
    }
    if (t < 64) { bs[t] = bk[t]; bs[64 + t] = bv[t]; gs[t] = ni_g[t]; bbeta[t] = ni_b[t]; }
    __syncthreads();

    int warp = t >> 5, lane = t & 31;
    const int ROWS_PER_BLOCK = 512;
    long base = (long)blockIdx.x * ROWS_PER_BLOCK;
    const float4* Ws4 = (const float4*)Ws;
    float4 bias = ((const float4*)bs)[lane];

    for (int it = 0; it < ROWS_PER_BLOCK / 32; ++it) {
        long r0 = base + (long)it * 32 + warp * 4;
        #pragma unroll
        for (int rr = 0; rr < 4; ++rr) {
            const float2 xv2 = ((const float2*)(inputs + (r0 + rr) * DD))[lane];
            float a = xv2.x, b2 = xv2.y;
            float s = a + b2;
            #pragma unroll
            for (int off = 16; off > 0; off >>= 1) s += __shfl_xor_sync(~0u, s, off);
            float m = s * (1.0f / 64.0f);
            float e0 = a - m, e1 = b2 - m;
            float ss = e0 * e0 + e1 * e1;
            #pragma unroll
            for (int off = 16; off > 0; off >>= 1) ss += __shfl_xor_sync(~0u, ss, off);
            float rstd = rsqrtf(ss * (1.0f / 64.0f) + 1e-5f);
            xs[warp][rr][2 * lane]     = e0 * rstd * gs[2 * lane] + bbeta[2 * lane];
            xs[warp][rr][2 * lane + 1] = e1 * rstd * gs[2 * lane + 1] + bbeta[2 * lane + 1];
        }
        __syncwarp();
        float4 acc0 = bias, acc1 = bias, acc2 = bias, acc3 = bias;
        #pragma unroll 8
        for (int d = 0; d < 64; ++d) {
            float4 w = Ws4[d * 33 + lane];
            float x0 = xs[warp][0][d], x1 = xs[warp][1][d];
            float x2 = xs[warp][2][d], x3 = xs[warp][3][d];
            acc0.x += x0 * w.x; acc0.y += x0 * w.y; acc0.z += x0 * w.z; acc0.w += x0 * w.w;
            acc1.x += x1 * w.x; acc1.y += x1 * w.y; acc1.z += x1 * w.z; acc1.w += x1 * w.w;
            acc2.x += x2 * w.x; acc2.y += x2 * w.y; acc2.z += x2 * w.z; acc2.w += x2 * w.w;
            acc3.x += x3 * w.x; acc3.y += x3 * w.y; acc3.z += x3 * w.z; acc3.w += x3 * w.w;
        }
        float4 accs[4] = {acc0, acc1, acc2, acc3};
        #pragma unroll
        for (int rr = 0; rr < 4; ++rr) {
            long r = r0 + rr;
            if (lane < 16) ((float4*)(g_k + r * DD))[lane] = accs[rr];
            else           ((float4*)(g_v + r * DD))[lane - 16] = accs[rr];
        }
        __syncwarp();
    }
}

// =======================================================================
// Kernel 2: init — prior MLP, posterior MLP on initial slots, reparam.
// One block per batch (8 rows), 256 threads.
// =======================================================================
__global__ __launch_bounds__(256) void init_kernel(
    const float* __restrict__ slots_in, const float* __restrict__ prior_slots,
    const float* __restrict__ eps_noise,
    const float* __restrict__ sr_W1, const float* __restrict__ sr_b1,
    const float* __restrict__ sr_W2, const float* __restrict__ sr_b2,
    const float* __restrict__ pr_W1, const float* __restrict__ pr_b1,
    const float* __restrict__ pr_W2, const float* __restrict__ pr_b2)
{
    __shared__ float s0[NS][64], p0[NS][64], ph[NS][128], tmp[NS][128];
    int b = blockIdx.x, t = threadIdx.x;
    for (int e = t; e < 512; e += 256) {
        int i = e >> 6, d = e & 63;
        s0[i][d] = slots_in[b * 512 + e];
        p0[i][d] = prior_slots[b * 512 + e];
    }
    __syncthreads();
    // prior hidden
    if (t < 128) {
        float a[NS]; 
        #pragma unroll
        for (int r = 0; r < NS; ++r) a[r] = 0.f;
        #pragma unroll 4
        for (int d = 0; d < 64; ++d) {
            float w = __ldg(pr_W1 + t * 64 + d);
            #pragma unroll
            for (int r = 0; r < NS; ++r) a[r] += p0[r][d] * w;
        }
        float b1 = pr_b1[t];
        #pragma unroll
        for (int r = 0; r < NS; ++r) ph[r][t] = fmaxf(a[r] + b1, 0.f);
    }
    __syncthreads();
    if (t < 128) {
        float a[NS];
        #pragma unroll
        for (int r = 0; r < NS; ++r) a[r] = 0.f;
        #pragma unroll 4
        for (int k = 0; k < 128; ++k) {
            float w = __ldg(pr_W2 + t * 128 + k);
            #pragma unroll
            for (int r = 0; r < NS; ++r) a[r] += ph[r][k] * w;
        }
        float b2 = pr_b2[t];
        #pragma unroll
        for (int r = 0; r < NS; ++r) g_prior[(b * NS + r) * 128 + t] = a[r] + b2;
    }
    __syncthreads();
    // posterior on initial slots
    if (t < 128) {
        float a[NS];
        #pragma unroll
        for (int r = 0; r < NS; ++r) a[r] = 0.f;
        #pragma unroll 4
        for (int d = 0; d < 64; ++d) {
            float w = __ldg(sr_W1 + t * 64 + d);
            #pragma unroll
            for (int r = 0; r < NS; ++r) a[r] += s0[r][d] * w;
        }
        float b1 = sr_b1[t];
        #pragma unroll
        for (int r = 0; r < NS; ++r) ph[r][t] = fmaxf(a[r] + b1, 0.f);
    }
    __syncthreads();
    if (t < 128) {
        float a[NS];
        #pragma unroll
        for (int r = 0; r < NS; ++r) a[r] = 0.f;
        #pragma unroll 4
        for (int k = 0; k < 128; ++k) {
            float w = __ldg(sr_W2 + t * 128 + k);
            #pragma unroll
            for (int r = 0; r < NS; ++r) a[r] += ph[r][k] * w;
        }
        float b2 = sr_b2[t];
        #pragma unroll
        for (int r = 0; r < NS; ++r) tmp[r][t] = a[r] + b2;
    }
    __syncthreads();
    for (int e = t; e < 512; e += 256) {
        int i = e >> 6, d = e & 63;
        float mu = tmp[i][d], lv = tmp[i][64 + d];
        g_slots[b * 512 + e] = eps_noise[b * 512 + e] * expf(0.5f * lv) + mu;
    }
    if (t < NS) g_kl[b * NS + t] = 0.f;
}

// =======================================================================
// Kernel 3: attention chunk. Block = (batch, chunk of 256 tokens).
// Computes q, streams k/v tiles of 64 tokens, softmax over 8 slots per
// token, accumulates partial numerator/denominator (deterministic).
// =======================================================================
__global__ __launch_bounds__(256) void attn_kernel(
    const float* __restrict__ Wq, const float* __restrict__ bq)
{
    __shared__ __align__(16) float qs[NS * 64];
    __shared__ float ss[NS * 64];
    __shared__ __align__(16) float kt[64 * 68];   // tile, padded rows (17 float4)
    __shared__ float wt[NS * 64];
    __shared__ __align__(16) float red[NS * 64];  // 512 floats for merges

    int b = blockIdx.x, c = blockIdx.y;
    int t = threadIdx.x;

    for (int e = t; e < 512; e += 256) ss[e] = g_slots[b * 512 + e];
    __syncthreads();

    // q = (slots @ Wq^T + bq) * SCALE
    for (int e = t; e < 512; e += 256) {
        int i = e >> 6, o = e & 63;
        float a = bq[o];
        const float* w = Wq + o * 64;
        const float* s = ss + i * 64;
        #pragma unroll 8
        for (int d = 0; d < 64; ++d) a += s[d] * __ldg(w + d);
        qs[e] = a * SCALE;
    }
    __syncthreads();

    int g  = t >> 7;        // token parity group for stage2
    int r  = t & 127;
    int ii = r >> 4;        // slot index for stage2
    int d4 = r & 15;        // float4 column for stage2
    float4 acc = {0.f, 0.f, 0.f, 0.f};
    float denp[NS];
    #pragma unroll
    for (int i = 0; i < NS; ++i) denp[i] = 0.f;

    const float4* kt4 = (const float4*)kt;
    const float4* qs4 = (const float4*)qs;

    for (int tt = 0; tt < JC / 64; ++tt) {
        long jb = (long)b * NTOK + (long)c * JC + tt * 64;
        __syncthreads();   // protect kt reuse
        for (int s5 = t; s5 < 1024; s5 += 256) {
            int j = s5 >> 4, dq = s5 & 15;
            ((float4*)(kt + j * 68))[dq] = ((const float4*)(g_k + (jb + j) * DD))[dq];
        }
        __syncthreads();
        // dots [8][64]
        for (int p = t; p < 512; p += 256) {
            int i = p >> 6, j = p & 63;
            float4 a4 = {0.f, 0.f, 0.f, 0.f};
            #pragma unroll
            for (int dq = 0; dq < 16; ++dq) {
                float4 q4 = qs4[i * 16 + dq];
                float4 k4 = kt4[j * 17 + dq];
                a4.x += q4.x * k4.x; a4.y += q4.y * k4.y;
                a4.z += q4.z * k4.z; a4.w += q4.w * k4.w;
            }
            wt[i * 64 + j] = (a4.x + a4.y) + (a4.z + a4.w);
        }
        __syncthreads();
        // softmax over the 8 slots, per token j=t
        if (t < 64) {
            float dv[NS]; float mx = -1e30f;
            #pragma unroll
            for (int i = 0; i < NS; ++i) { dv[i] = wt[i * 64 + t]; mx = fmaxf(mx, dv[i]); }
            float sum = 0.f;
            #pragma unroll
            for (int i = 0; i < NS; ++i) { dv[i] = expf(dv[i] - mx); sum += dv[i]; }
            float inv = 1.0f / sum;
            #pragma unroll
            for (int i = 0; i < NS; ++i) {
                float w = dv[i] * inv + EPSA;
                wt[i * 64 + t] = w;
                denp[i] += w;
            }
        }
        __syncthreads();
        // v tile (overwrites kt)
        for (int s5 = t; s5 < 1024; s5 += 256) {
            int j = s5 >> 4, dq = s5 & 15;
            ((float4*)(kt + j * 68))[dq] = ((const float4*)(g_v + (jb + j) * DD))[dq];
        }
        __syncthreads();
        // weighted accumulation
        #pragma unroll 8
        for (int jj = 0; jj < 32; ++jj) {
            int j = jj * 2 + g;
            float w = wt[ii * 64 + j];
            float4 v4 = kt4[j * 17 + d4];
            acc.x += w * v4.x; acc.y += w * v4.y; acc.z += w * v4.z; acc.w += w * v4.w;
        }
    }
    __syncthreads();
    if (g == 1) ((float4*)red)[r] = acc;
    __syncthreads();
    if (g == 0) {
        float4 o4 = ((float4*)red)[r];
        acc.x += o4.x; acc.y += o4.y; acc.z += o4.z; acc.w += o4.w;
        ((float4*)(g_pnum + (((long)b * NCH + c) * NS + ii) * DD))[d4] = acc;
    }
    __syncthreads();
    if (t < 64) {
        #pragma unroll
        for (int i = 0; i < NS; ++i) wt[i * 64 + t] = denp[i];
    }
    __syncthreads();
    if (t < NS) {
        float s = 0.f;
        for (int j = 0; j < 64; ++j) s += wt[t * 64 + j];
        g_pden[((long)b * NCH + c) * NS + t] = s;
    }
}

// =======================================================================
// Kernel 4: per-batch fused update: reduce partials -> GRU -> LN -> MLP
// residual -> posterior MLP -> KL accumulation. Block = batch, 256 thr.
// =======================================================================
__global__ __launch_bounds__(256) void update_kernel(
    const float* __restrict__ gru_Wih, const float* __restrict__ gru_Whh,
    const float* __restrict__ gru_bih, const float* __restrict__ gru_bhh,
    const float* __restrict__ npf_g,  const float* __restrict__ npf_b,
    const float* __restrict__ mlp_W1, const float* __restrict__ mlp_b1,
    const float* __restrict__ mlp_W2, const float* __restrict__ mlp_b2,
    const float* __restrict__ sr_W1,  const float* __restrict__ sr_b1,
    const float* __restrict__ sr_W2,  const float* __restrict__ sr_b2)
{
    __shared__ float u[NS][64], h[NS][64], hn[NS][64], lnx[NS][64], sn[NS][64];
    __shared__ float gi[NS][192], gh[NS][192];
    __shared__ float hid[NS][128], ph[NS][128], post[NS][128];
    int b = blockIdx.x, t = threadIdx.x;

    for (int e = t; e < 512; e += 256) {
        int i = e >> 6, d = e & 63;
        h[i][d] = g_slots[b * 512 + e];
        float s = 0.f, den = 0.f;
        for (int c = 0; c < NCH; ++c) {
            s   += g_pnum[(((long)b * NCH + c) * NS + i) * DD + d];
            den += g_pden[((long)b * NCH + c) * NS + i];
        }
        u[i][d] = s / den;
    }
    __syncthreads();

    if (t < 192) {
        float ai[NS], ah[NS];
        #pragma unroll
        for (int r5 = 0; r5 < NS; ++r5) { ai[r5] = 0.f; ah[r5] = 0.f; }
        const float* wi = gru_Wih + t * 64;
        const float* wh = gru_Whh + t * 64;
        #pragma unroll 4
        for (int d = 0; d < 64; ++d) {
            float wiv = __ldg(wi + d), whv = __ldg(wh + d);
            #pragma unroll
            for (int r5 = 0; r5 < NS; ++r5) { ai[r5] += u[r5][d] * wiv; ah[r5] += h[r5][d] * whv; }
        }
        float bi = gru_bih[t], bh = gru_bhh[t];
        #pragma unroll
        for (int r5 = 0; r5 < NS; ++r5) { gi[r5][t] = ai[r5] + bi; gh[r5][t] = ah[r5] + bh; }
    }
    __syncthreads();

    for (int e = t; e < 512; e += 256) {
        int i = e >> 6, d = e & 63;
        float rg = 1.f / (1.f + expf(-(gi[i][d] + gh[i][d])));
        float z  = 1.f / (1.f + expf(-(gi[i][64 + d] + gh[i][64 + d])));
        float n  = tanhf(gi[i][128 + d] + rg * gh[i][128 + d]);
        hn[i][d] = (1.f - z) * n + z * h[i][d];
    }
    __syncthreads();

    {   // LN per row: one warp per slot-row
        int r5 = t >> 5, lane = t & 31;
        float a = hn[r5][lane], b2 = hn[r5][lane + 32];
        float s = a + b2;
        #pragma unroll
        for (int off = 16; off > 0; off >>= 1) s += __shfl_xor_sync(~0u, s, off);
        float m = s * (1.f / 64.f);
        float e0 = a - m, e1 = b2 - m;
        float ss2 = e0 * e0 + e1 * e1;
        #pragma unroll
        for (int off = 16; off > 0; off >>= 1) ss2 += __shfl_xor_sync(~0u, ss2, off);
        float rstd = rsqrtf(ss2 * (1.f / 64.f) + 1e-5f);
        lnx[r5][lane]      = e0 * rstd * npf_g[lane] + npf_b[lane];
        lnx[r5][lane + 32] = e1 * rstd * npf_g[lane + 32] + npf_b[lane + 32];
    }
    __syncthreads();

    if (t < 128) {
        float a[NS];
        #pragma unroll
        for (int r5 = 0; r5 < NS; ++r5) a[r5] = 0.f;
        #pragma unroll 4
        for (int d = 0; d < 64; ++d) {
            float w = __ldg(mlp_W1 + t * 64 + d);
            #pragma unroll
            for (int r5 = 0; r5 < NS; ++r5) a[r5] += lnx[r5][d] * w;
        }
        float b1 = mlp_b1[t];
        #pragma unroll
        for (int r5 = 0; r5 < NS; ++r5) hid[r5][t] = fmaxf(a[r5] + b1, 0.f);
    }
    __syncthreads();

    if (t < 64) {
        float a[NS];
        #pragma unroll
        for (int r5 = 0; r5 < NS; ++r5) a[r5] = 0.f;
        #pragma unroll 4
        for (int k = 0; k < 128; ++k) {
            float w = __ldg(mlp_W2 + t * 128 + k);
            #pragma unroll
            for (int r5 = 0; r5 < NS; ++r5) a[r5] += hid[r5][k] * w;
        }
        float b2 = mlp_b2[t];
        #pragma unroll
        for (int r5 = 0; r5 < NS; ++r5) {
            float v = hn[r5][t] + a[r5] + b2;
            sn[r5][t] = v;
            g_slots[b * 512 + r5 * 64 + t] = v;
        }
    }
    __syncthreads();

    if (t < 128) {
        float a[NS];
        #pragma unroll
        for (int r5 = 0; r5 < NS; ++r5) a[r5] = 0.f;
        #pragma unroll 4
        for (int d = 0; d < 64; ++d) {
            float w = __ldg(sr_W1 + t * 64 + d);
            #pragma unroll
            for (int r5 = 0; r5 < NS; ++r5) a[r5] += sn[r5][d] * w;
        }
        float b1 = sr_b1[t];
        #pragma unroll
        for (int r5 = 0; r5 < NS; ++r5) ph[r5][t] = fmaxf(a[r5] + b1, 0.f);
    }
    __syncthreads();

    if (t < 128) {
        float a[NS];
        #pragma unroll
        for (int r5 = 0; r5 < NS; ++r5) a[r5] = 0.f;
        #pragma unroll 4
        for (int k = 0; k < 128; ++k) {
            float w = __ldg(sr_W2 + t * 128 + k);
            #pragma unroll
            for (int r5 = 0; r5 < NS; ++r5) a[r5] += ph[r5][k] * w;
        }
        float b2 = sr_b2[t];
        #pragma unroll
        for (int r5 = 0; r5 < NS; ++r5) post[r5][t] = a[r5] + b2;
    }
    __syncthreads();

    {   // KL: one warp per row
        int r5 = t >> 5, lane = t & 31;
        float term = 0.f;
        #pragma unroll
        for (int q = 0; q < 2; ++q) {
            int d = lane + q * 32;
            float m_po = post[r5][d], lv_po = post[r5][64 + d];
            float m_pr = g_prior[(b * NS + r5) * 128 + d];
            float lv_pr = g_prior[(b * NS + r5) * 128 + 64 + d];
            float dm = m_po - m_pr;
            term += lv_pr - lv_po + (expf(lv_po) + dm * dm) * expf(-lv_pr) - 1.0f;
        }
        #pragma unroll
        for (int off = 16; off > 0; off >>= 1) term += __shfl_xor_sync(~0u, term, off);
        if (lane == 0) g_kl[b * NS + r5] += 0.5f * term;
    }
}

// =======================================================================
// Kernel 5: pack outputs: [slots (131072) | kl (2048)]
// =======================================================================
__global__ void out_kernel(float* __restrict__ out, int n)
{
    int idx = blockIdx.x * blockDim.x + threadIdx.x;
    if (idx >= n) return;
    if (idx < BATCH * NS * DD) out[idx] = g_slots[idx];
    else {
        int r = idx - BATCH * NS * DD;
        out[idx] = (r < BATCH * NS) ? g_kl[r] : 0.0f;
    }
}

// =======================================================================
extern "C" void kernel_launch(void* const* d_in, const int* in_sizes, int n_in,
                              void* d_out, int out_size)
{
    const float* inputs      = (const float*)d_in[0];
    const float* slots       = (const float*)d_in[1];
    const float* prior_slots = (const float*)d_in[2];
    const float* eps_noise   = (const float*)d_in[3];
    const float* ni_g  = (const float*)d_in[4];
    const float* ni_b  = (const float*)d_in[5];
    const float* npf_g = (const float*)d_in[6];
    const float* npf_b = (const float*)d_in[7];
    const float* Wq = (const float*)d_in[8];
    const float* bq = (const float*)d_in[9];
    const float* Wk = (const float*)d_in[10];
    const float* bk = (const float*)d_in[11];
    const float* Wv = (const float*)d_in[12];
    const float* bv = (const float*)d_in[13];
    const float* sr_W1 = (const float*)d_in[14];
    const float* sr_b1 = (const float*)d_in[15];
    const float* sr_W2 = (const float*)d_in[16];
    const float* sr_b2 = (const float*)d_in[17];
    const float* pr_W1 = (const float*)d_in[18];
    const float* pr_b1 = (const float*)d_in[19];
    const float* pr_W2 = (const float*)d_in[20];
    const float* pr_b2 = (const float*)d_in[21];
    const float* gru_Wih = (const float*)d_in[22];
    const float* gru_Whh = (const float*)d_in[23];
    const float* gru_bih = (const float*)d_in[24];
    const float* gru_bhh = (const float*)d_in[25];
    const float* mlp_W1 = (const float*)d_in[26];
    const float* mlp_b1 = (const float*)d_in[27];
    const float* mlp_W2 = (const float*)d_in[28];
    const float* mlp_b2 = (const float*)d_in[29];

    // 1M rows / 512 rows per block
    kv_kernel<<<2048, 256>>>(inputs, ni_g, ni_b, Wk, bk, Wv, bv);
    init_kernel<<<BATCH, 256>>>(slots, prior_slots, eps_noise,
                                sr_W1, sr_b1, sr_W2, sr_b2,
                                pr_W1, pr_b1, pr_W2, pr_b2);
    for (int it = 0; it < 3; ++it) {
        attn_kernel<<<dim3(BATCH, NCH), 256>>>(Wq, bq);
        update_kernel<<<BATCH, 256>>>(gru_Wih, gru_Whh, gru_bih, gru_bhh,
                                      npf_g, npf_b,
                                      mlp_W1, mlp_b1, mlp_W2, mlp_b2,
                                      sr_W1, sr_b1, sr_W2, sr_b2);
    }
    out_kernel<<<(out_size + 255) / 256, 256>>>((float*)d_out, out_size);
}

// round 7
// speedup vs baseline: 2.5823x; 2.5823x over previous
#include <cuda_runtime.h>

#define NBATCH 256
#define NTOK   4096
#define NS     8
#define DD     64
#define SCALEF 0.125f
#define EPSA   1e-8f
#define NTILE  64          // tokens per tile
#define TILES  (NTOK / NTILE)

// ---- dynamic shared layout (float offsets) ----
#define O_SL    0          // slots [8][64]
#define O_QP    512        // q' (x-space, scaled) [8][64]
#define O_QC    1024       // qc [8]
#define O_DINV  1032       // 1/den [8]
#define O_KL    1040       // kl accum [8]
#define O_GSH   1048       // ni gamma [64]
#define O_BSH   1112       // ni beta  [64]
#define O_NPG   1176       // npf gamma [64]
#define O_NPB   1240       // npf beta  [64]
#define O_PRIOR 1304       // prior [8][128]
#define O_NUM   2328       // numerator [8][64]
#define O_SCR   2848       // scratch union base
// attention scratch
#define O_KT0   (O_SCR)           // tile buf 0: [64][68]
#define O_KT1   (O_SCR + 4352)    // tile buf 1
#define O_WT    (O_SCR + 8704)    // dots/weights [8][64]  (also qtmp)
#define O_RED   (O_SCR + 9216)    // group reduce 3*512
// update scratch (aliases KT region)
#define O_U     (O_SCR)
#define O_GI    (O_SCR + 512)
#define O_GH    (O_SCR + 2048)
#define O_HN    (O_SCR + 3584)
#define O_LNX   (O_SCR + 4096)
#define O_HID   (O_SCR + 4608)
#define O_PH    (O_SCR + 5632)
#define O_POST  (O_SCR + 6656)
// init scratch (aliases KT region)
#define O_P0    (O_SCR)
#define O_PHI   (O_SCR + 512)
#define O_T2    (O_SCR + 1536)

#define SMEM_FLOATS 13600
#define SMEM_BYTES  (SMEM_FLOATS * 4)

__device__ __forceinline__ void cp16(float* smem_dst, const float* gsrc) {
    unsigned dst = (unsigned)__cvta_generic_to_shared(smem_dst);
    asm volatile("cp.async.cg.shared.global [%0], [%1], 16;\n" :: "r"(dst), "l"(gsrc));
}
__device__ __forceinline__ void cp_commit() { asm volatile("cp.async.commit_group;\n"); }

__device__ __forceinline__ float sigmoidf_(float x) { return 1.0f / (1.0f + expf(-x)); }

__global__ __launch_bounds__(512, 2) void mega_kernel(
    const float* __restrict__ inputs,
    const float* __restrict__ slots_in,
    const float* __restrict__ prior_slots,
    const float* __restrict__ eps_noise,
    const float* __restrict__ ni_g,  const float* __restrict__ ni_b,
    const float* __restrict__ npf_g, const float* __restrict__ npf_b,
    const float* __restrict__ Wq, const float* __restrict__ bq,
    const float* __restrict__ Wk, const float* __restrict__ bk,
    const float* __restrict__ Wv, const float* __restrict__ bv,
    const float* __restrict__ sr_W1, const float* __restrict__ sr_b1,
    const float* __restrict__ sr_W2, const float* __restrict__ sr_b2,
    const float* __restrict__ pr_W1, const float* __restrict__ pr_b1,
    const float* __restrict__ pr_W2, const float* __restrict__ pr_b2,
    const float* __restrict__ gru_Wih, const float* __restrict__ gru_Whh,
    const float* __restrict__ gru_bih, const float* __restrict__ gru_bhh,
    const float* __restrict__ mlp_W1, const float* __restrict__ mlp_b1,
    const float* __restrict__ mlp_W2, const float* __restrict__ mlp_b2,
    float* __restrict__ out)
{
    extern __shared__ float sm[];
    const int b = blockIdx.x;
    const int t = threadIdx.x;

    float* SLs   = sm + O_SL;
    float* QPs   = sm + O_QP;
    float* QCs   = sm + O_QC;
    float* DINVs = sm + O_DINV;
    float* KLs   = sm + O_KL;
    float* PRIORs= sm + O_PRIOR;
    float* NUMs  = sm + O_NUM;
    float* WTs   = sm + O_WT;

    // ---------------- init ----------------
    {
        SLs[t]            = slots_in[(long)b * 512 + t];
        (sm + O_P0)[t]    = prior_slots[(long)b * 512 + t];
        if (t < 64) {
            (sm + O_GSH)[t] = ni_g[t];  (sm + O_BSH)[t] = ni_b[t];
            (sm + O_NPG)[t] = npf_g[t]; (sm + O_NPB)[t] = npf_b[t];
        }
        if (t < 8) KLs[t] = 0.f;
        __syncthreads();
        // prior hidden: relu(P0 @ pr_W1^T + b1), 2 rows per thread
        {
            int m = t & 127, ip = t >> 7, i0 = ip * 2;
            float ax = 0.f, ay = 0.f;
            const float* wr = pr_W1 + m * 64;
            #pragma unroll 8
            for (int d = 0; d < 64; ++d) {
                float w = __ldg(wr + d);
                ax += (sm + O_P0)[i0 * 64 + d] * w;
                ay += (sm + O_P0)[(i0 + 1) * 64 + d] * w;
            }
            float b1 = __ldg(pr_b1 + m);
            (sm + O_PHI)[i0 * 128 + m]       = fmaxf(ax + b1, 0.f);
            (sm + O_PHI)[(i0 + 1) * 128 + m] = fmaxf(ay + b1, 0.f);
        }
        __syncthreads();
        {
            int m = t & 127, ip = t >> 7, i0 = ip * 2;
            float ax = 0.f, ay = 0.f;
            const float* wr = pr_W2 + m * 128;
            #pragma unroll 8
            for (int k = 0; k < 128; ++k) {
                float w = __ldg(wr + k);
                ax += (sm + O_PHI)[i0 * 128 + k] * w;
                ay += (sm + O_PHI)[(i0 + 1) * 128 + k] * w;
            }
            float b2 = __ldg(pr_b2 + m);
            PRIORs[i0 * 128 + m]       = ax + b2;
            PRIORs[(i0 + 1) * 128 + m] = ay + b2;
        }
        __syncthreads();
        // posterior hidden on initial slots
        {
            int m = t & 127, ip = t >> 7, i0 = ip * 2;
            float ax = 0.f, ay = 0.f;
            const float* wr = sr_W1 + m * 64;
            #pragma unroll 8
            for (int d = 0; d < 64; ++d) {
                float w = __ldg(wr + d);
                ax += SLs[i0 * 64 + d] * w;
                ay += SLs[(i0 + 1) * 64 + d] * w;
            }
            float b1 = __ldg(sr_b1 + m);
            (sm + O_PHI)[i0 * 128 + m]       = fmaxf(ax + b1, 0.f);
            (sm + O_PHI)[(i0 + 1) * 128 + m] = fmaxf(ay + b1, 0.f);
        }
        __syncthreads();
        {
            int m = t & 127, ip = t >> 7, i0 = ip * 2;
            float ax = 0.f, ay = 0.f;
            const float* wr = sr_W2 + m * 128;
            #pragma unroll 8
            for (int k = 0; k < 128; ++k) {
                float w = __ldg(wr + k);
                ax += (sm + O_PHI)[i0 * 128 + k] * w;
                ay += (sm + O_PHI)[(i0 + 1) * 128 + k] * w;
            }
            float b2 = __ldg(sr_b2 + m);
            (sm + O_T2)[i0 * 128 + m]       = ax + b2;
            (sm + O_T2)[(i0 + 1) * 128 + m] = ay + b2;
        }
        __syncthreads();
        {   // reparameterize
            int i = t >> 6, d = t & 63;
            float mu = (sm + O_T2)[i * 128 + d];
            float lv = (sm + O_T2)[i * 128 + 64 + d];
            SLs[t] = eps_noise[(long)b * 512 + t] * expf(0.5f * lv) + mu;
        }
        __syncthreads();
    }

    // ---------------- iterations ----------------
    for (int iter = 0; iter < 3; ++iter) {
        // prefetch tile 0 (into KT0) — overlaps q projection
        {
            const float* src = inputs + ((long)b * NTOK) * DD;
            float* kb = sm + O_KT0;
            int m0 = t, m1 = t + 512;
            cp16(kb + ((m0 >> 4) * 68 + (m0 & 15) * 4), src + m0 * 4);
            cp16(kb + ((m1 >> 4) * 68 + (m1 & 15) * 4), src + m1 * 4);
            cp_commit();
        }
        // q = slots@Wq^T + bq  (store to WTs as qtmp)
        {
            int i = t >> 6, o = t & 63;
            float a = __ldg(bq + o);
            const float* wr = Wq + o * 64;
            #pragma unroll 8
            for (int d = 0; d < 64; ++d) a += SLs[i * 64 + d] * __ldg(wr + d);
            WTs[i * 64 + o] = a;
        }
        __syncthreads();
        // q' = SCALE * (Wk^T q); qc = SCALE * (q . bk)
        {
            int i = t >> 6, d = t & 63;
            float a = 0.f;
            #pragma unroll 8
            for (int o = 0; o < 64; ++o) a += WTs[i * 64 + o] * __ldg(Wk + o * 64 + d);
            QPs[i * 64 + d] = a * SCALEF;
        }
        if (t < 8) {
            float a = 0.f;
            #pragma unroll 8
            for (int o = 0; o < 64; ++o) a += WTs[t * 64 + o] * __ldg(bk + o);
            QCs[t] = a * SCALEF;
        }
        __syncthreads();

        // per-thread accumulators
        const int g  = t >> 7;       // token group (4)
        const int r  = t & 127;
        const int ii = r >> 4;       // slot
        const int d4 = r & 15;       // float4 column
        float4 accv = {0.f, 0.f, 0.f, 0.f};
        float denp[NS];
        #pragma unroll
        for (int i = 0; i < NS; ++i) denp[i] = 0.f;

        const float4* qp4 = (const float4*)QPs;

        for (int tt = 0; tt < TILES; ++tt) {
            float* ktb = sm + ((tt & 1) ? O_KT1 : O_KT0);
            float4* kt4 = (float4*)ktb;
            // prefetch next tile into other buffer
            if (tt < TILES - 1) {
                const float* src = inputs + ((long)b * NTOK + (long)(tt + 1) * NTILE) * DD;
                float* kb = sm + (((tt + 1) & 1) ? O_KT1 : O_KT0);
                int m0 = t, m1 = t + 512;
                cp16(kb + ((m0 >> 4) * 68 + (m0 & 15) * 4), src + m0 * 4);
                cp16(kb + ((m1 >> 4) * 68 + (m1 & 15) * 4), src + m1 * 4);
                cp_commit();
                asm volatile("cp.async.wait_group 1;\n");
            } else {
                asm volatile("cp.async.wait_group 0;\n");
            }
            __syncthreads();

            // ---- LN in place (8 threads per token) ----
            {
                int jt = t >> 3, qq = t & 7;
                float4* row = kt4 + jt * 17;
                float4 a0 = row[qq], a1 = row[qq + 8];
                float s = a0.x + a0.y + a0.z + a0.w + a1.x + a1.y + a1.z + a1.w;
                s += __shfl_xor_sync(~0u, s, 1);
                s += __shfl_xor_sync(~0u, s, 2);
                s += __shfl_xor_sync(~0u, s, 4);
                float m = s * (1.f / 64.f);
                a0.x -= m; a0.y -= m; a0.z -= m; a0.w -= m;
                a1.x -= m; a1.y -= m; a1.z -= m; a1.w -= m;
                float ss = a0.x * a0.x + a0.y * a0.y + a0.z * a0.z + a0.w * a0.w
                         + a1.x * a1.x + a1.y * a1.y + a1.z * a1.z + a1.w * a1.w;
                ss += __shfl_xor_sync(~0u, ss, 1);
                ss += __shfl_xor_sync(~0u, ss, 2);
                ss += __shfl_xor_sync(~0u, ss, 4);
                float rstd = rsqrtf(ss * (1.f / 64.f) + 1e-5f);
                float4 g0 = ((const float4*)(sm + O_GSH))[qq];
                float4 g1 = ((const float4*)(sm + O_GSH))[qq + 8];
                float4 b0 = ((const float4*)(sm + O_BSH))[qq];
                float4 b1 = ((const float4*)(sm + O_BSH))[qq + 8];
                a0.x = a0.x * rstd * g0.x + b0.x; a0.y = a0.y * rstd * g0.y + b0.y;
                a0.z = a0.z * rstd * g0.z + b0.z; a0.w = a0.w * rstd * g0.w + b0.w;
                a1.x = a1.x * rstd * g1.x + b1.x; a1.y = a1.y * rstd * g1.y + b1.y;
                a1.z = a1.z * rstd * g1.z + b1.z; a1.w = a1.w * rstd * g1.w + b1.w;
                row[qq] = a0; row[qq + 8] = a1;
            }
            __syncthreads();

            // ---- dots: [8 slots][64 tokens] ----
            {
                int di = t >> 6, dj = t & 63;
                const float4* qrow = qp4 + di * 16;
                const float4* krow = kt4 + dj * 17;
                float4 a4 = {0.f, 0.f, 0.f, 0.f};
                #pragma unroll
                for (int dq = 0; dq < 16; ++dq) {
                    float4 q4 = qrow[dq];
                    float4 k4 = krow[dq];
                    a4.x += q4.x * k4.x; a4.y += q4.y * k4.y;
                    a4.z += q4.z * k4.z; a4.w += q4.w * k4.w;
                }
                WTs[di * 64 + dj] = (a4.x + a4.y) + (a4.z + a4.w) + QCs[di];
            }
            __syncthreads();

            // ---- softmax over slots per token ----
            if (t < NTILE) {
                float dv[NS]; float mx = -1e30f;
                #pragma unroll
                for (int i = 0; i < NS; ++i) { dv[i] = WTs[i * 64 + t]; mx = fmaxf(mx, dv[i]); }
                float sum = 0.f;
                #pragma unroll
                for (int i = 0; i < NS; ++i) { dv[i] = expf(dv[i] - mx); sum += dv[i]; }
                float inv = 1.0f / sum;
                #pragma unroll
                for (int i = 0; i < NS; ++i) {
                    float w = dv[i] * inv + EPSA;
                    WTs[i * 64 + t] = w;
                    denp[i] += w;
                }
            }
            __syncthreads();

            // ---- accumulate numerator (x-space) ----
            #pragma unroll 4
            for (int jj = 0; jj < 16; ++jj) {
                int j = jj * 4 + g;
                float w = WTs[ii * 64 + j];
                float4 v4 = kt4[j * 17 + d4];
                accv.x += w * v4.x; accv.y += w * v4.y;
                accv.z += w * v4.z; accv.w += w * v4.w;
            }
            __syncthreads();
        }

        // ---- reduce groups -> NUM, den -> DINV ----
        if (g > 0) ((float4*)(sm + O_RED))[(g - 1) * 128 + r] = accv;
        __syncthreads();
        if (g == 0) {
            float4 s = accv;
            #pragma unroll
            for (int gg = 0; gg < 3; ++gg) {
                float4 o4 = ((float4*)(sm + O_RED))[gg * 128 + r];
                s.x += o4.x; s.y += o4.y; s.z += o4.z; s.w += o4.w;
            }
            ((float4*)NUMs)[ii * 16 + d4] = s;
        }
        if (t < NTILE) {
            #pragma unroll
            for (int i = 0; i < NS; ++i) WTs[i * 64 + t] = denp[i];
        }
        __syncthreads();
        if (t < 8) {
            float s = 0.f;
            #pragma unroll 8
            for (int j = 0; j < 64; ++j) s += WTs[t * 64 + j];
            DINVs[t] = 1.0f / s;
        }
        __syncthreads();

        // ---- u = Wv (num/den) + bv ----
        {
            int i = t >> 6, o = t & 63;
            float a = 0.f;
            const float* wr = Wv + o * 64;
            #pragma unroll 8
            for (int d = 0; d < 64; ++d) a += NUMs[i * 64 + d] * __ldg(wr + d);
            (sm + O_U)[i * 64 + o] = a * DINVs[i] + __ldg(bv + o);
        }
        __syncthreads();

        // ---- GRU gates ----
        if (t < 384) {
            int o = (t < 192) ? t : t - 192;
            const float* wr = ((t < 192) ? gru_Wih : gru_Whh) + o * 64;
            const float* xr = (t < 192) ? (sm + O_U) : SLs;
            float a[NS];
            #pragma unroll
            for (int i = 0; i < NS; ++i) a[i] = 0.f;
            #pragma unroll 4
            for (int d = 0; d < 64; ++d) {
                float w = __ldg(wr + d);
                #pragma unroll
                for (int i = 0; i < NS; ++i) a[i] += xr[i * 64 + d] * w;
            }
            float bb = (t < 192) ? __ldg(gru_bih + o) : __ldg(gru_bhh + o);
            float* dst = (t < 192) ? (sm + O_GI) : (sm + O_GH);
            #pragma unroll
            for (int i = 0; i < NS; ++i) dst[i * 192 + o] = a[i] + bb;
        }
        __syncthreads();
        {
            int i = t >> 6, d = t & 63;
            float gi0 = (sm + O_GI)[i * 192 + d],       gh0 = (sm + O_GH)[i * 192 + d];
            float gi1 = (sm + O_GI)[i * 192 + 64 + d],  gh1 = (sm + O_GH)[i * 192 + 64 + d];
            float gi2 = (sm + O_GI)[i * 192 + 128 + d], gh2 = (sm + O_GH)[i * 192 + 128 + d];
            float rg = sigmoidf_(gi0 + gh0);
            float z  = sigmoidf_(gi1 + gh1);
            float n  = tanhf(gi2 + rg * gh2);
            (sm + O_HN)[t] = (1.f - z) * n + z * SLs[t];
        }
        __syncthreads();
        // ---- LN(hn) with npf ----
        if (t < 256) {
            int i = t >> 5, lane = t & 31;
            float a = (sm + O_HN)[i * 64 + lane], b2 = (sm + O_HN)[i * 64 + lane + 32];
            float s = a + b2;
            #pragma unroll
            for (int off = 16; off > 0; off >>= 1) s += __shfl_xor_sync(~0u, s, off);
            float m = s * (1.f / 64.f);
            float e0 = a - m, e1 = b2 - m;
            float ss = e0 * e0 + e1 * e1;
            #pragma unroll
            for (int off = 16; off > 0; off >>= 1) ss += __shfl_xor_sync(~0u, ss, off);
            float rstd = rsqrtf(ss * (1.f / 64.f) + 1e-5f);
            (sm + O_LNX)[i * 64 + lane]      = e0 * rstd * (sm + O_NPG)[lane]      + (sm + O_NPB)[lane];
            (sm + O_LNX)[i * 64 + lane + 32] = e1 * rstd * (sm + O_NPG)[lane + 32] + (sm + O_NPB)[lane + 32];
        }
        __syncthreads();
        // ---- mlp hidden ----
        {
            int m = t & 127, ip = t >> 7, i0 = ip * 2;
            float ax = 0.f, ay = 0.f;
            const float* wr = mlp_W1 + m * 64;
            #pragma unroll 8
            for (int d = 0; d < 64; ++d) {
                float w = __ldg(wr + d);
                ax += (sm + O_LNX)[i0 * 64 + d] * w;
                ay += (sm + O_LNX)[(i0 + 1) * 64 + d] * w;
            }
            float b1 = __ldg(mlp_b1 + m);
            (sm + O_HID)[i0 * 128 + m]       = fmaxf(ax + b1, 0.f);
            (sm + O_HID)[(i0 + 1) * 128 + m] = fmaxf(ay + b1, 0.f);
        }
        __syncthreads();
        // ---- mlp out + residual -> new slots ----
        {
            int i = t >> 6, d = t & 63;
            float a = 0.f;
            const float* wr = mlp_W2 + d * 128;
            #pragma unroll 8
            for (int k = 0; k < 128; ++k) a += (sm + O_HID)[i * 128 + k] * __ldg(wr + k);
            SLs[t] = (sm + O_HN)[t] + a + __ldg(mlp_b2 + d);
        }
        __syncthreads();
        // ---- posterior MLP ----
        {
            int m = t & 127, ip = t >> 7, i0 = ip * 2;
            float ax = 0.f, ay = 0.f;
            const float* wr = sr_W1 + m * 64;
            #pragma unroll 8
            for (int d = 0; d < 64; ++d) {
                float w = __ldg(wr + d);
                ax += SLs[i0 * 64 + d] * w;
                ay += SLs[(i0 + 1) * 64 + d] * w;
            }
            float b1 = __ldg(sr_b1 + m);
            (sm + O_PH)[i0 * 128 + m]       = fmaxf(ax + b1, 0.f);
            (sm + O_PH)[(i0 + 1) * 128 + m] = fmaxf(ay + b1, 0.f);
        }
        __syncthreads();
        {
            int m = t & 127, ip = t >> 7, i0 = ip * 2;
            float ax = 0.f, ay = 0.f;
            const float* wr = sr_W2 + m * 128;
            #pragma unroll 8
            for (int k = 0; k < 128; ++k) {
                float w = __ldg(wr + k);
                ax += (sm + O_PH)[i0 * 128 + k] * w;
                ay += (sm + O_PH)[(i0 + 1) * 128 + k] * w;
            }
            float b2 = __ldg(sr_b2 + m);
            (sm + O_POST)[i0 * 128 + m]       = ax + b2;
            (sm + O_POST)[(i0 + 1) * 128 + m] = ay + b2;
        }
        __syncthreads();
        // ---- KL ----
        if (t < 256) {
            int i = t >> 5, lane = t & 31;
            float term = 0.f;
            #pragma unroll
            for (int q = 0; q < 2; ++q) {
                int d = lane + q * 32;
                float m_po = (sm + O_POST)[i * 128 + d];
                float lv_po = (sm + O_POST)[i * 128 + 64 + d];
                float m_pr = PRIORs[i * 128 + d];
                float lv_pr = PRIORs[i * 128 + 64 + d];
                float dm = m_po - m_pr;
                term += lv_pr - lv_po + (expf(lv_po) + dm * dm) * expf(-lv_pr) - 1.0f;
            }
            #pragma unroll
            for (int off = 16; off > 0; off >>= 1) term += __shfl_xor_sync(~0u, term, off);
            if (lane == 0) KLs[i] += 0.5f * term;
        }
        __syncthreads();
    }

    // ---------------- output ----------------
    out[(long)b * 512 + t] = SLs[t];
    if (t < 8) out[131072 + b * 8 + t] = KLs[t];
}

extern "C" void kernel_launch(void* const* d_in, const int* in_sizes, int n_in,
                              void* d_out, int out_size)
{
    const float* inputs      = (const float*)d_in[0];
    const float* slots       = (const float*)d_in[1];
    const float* prior_slots = (const float*)d_in[2];
    const float* eps_noise   = (const float*)d_in[3];
    const float* ni_g  = (const float*)d_in[4];
    const float* ni_b  = (const float*)d_in[5];
    const float* npf_g = (const float*)d_in[6];
    const float* npf_b = (const float*)d_in[7];
    const float* Wq = (const float*)d_in[8];
    const float* bq = (const float*)d_in[9];
    const float* Wk = (const float*)d_in[10];
    const float* bk = (const float*)d_in[11];
    const float* Wv = (const float*)d_in[12];
    const float* bv = (const float*)d_in[13];
    const float* sr_W1 = (const float*)d_in[14];
    const float* sr_b1 = (const float*)d_in[15];
    const float* sr_W2 = (const float*)d_in[16];
    const float* sr_b2 = (const float*)d_in[17];
    const float* pr_W1 = (const float*)d_in[18];
    const float* pr_b1 = (const float*)d_in[19];
    const float* pr_W2 = (const float*)d_in[20];
    const float* pr_b2 = (const float*)d_in[21];
    const float* gru_Wih = (const float*)d_in[22];
    const float* gru_Whh = (const float*)d_in[23];
    const float* gru_bih = (const float*)d_in[24];
    const float* gru_bhh = (const float*)d_in[25];
    const float* mlp_W1 = (const float*)d_in[26];
    const float* mlp_b1 = (const float*)d_in[27];
    const float* mlp_W2 = (const float*)d_in[28];
    const float* mlp_b2 = (const float*)d_in[29];

    cudaFuncSetAttribute(mega_kernel, cudaFuncAttributeMaxDynamicSharedMemorySize, SMEM_BYTES);

    mega_kernel<<<NBATCH, 512, SMEM_BYTES>>>(
        inputs, slots, prior_slots, eps_noise,
        ni_g, ni_b, npf_g, npf_b,
        Wq, bq, Wk, bk, Wv, bv,
        sr_W1, sr_b1, sr_W2, sr_b2,
        pr_W1, pr_b1, pr_W2, pr_b2,
        gru_Wih, gru_Whh, gru_bih, gru_bhh,
        mlp_W1, mlp_b1, mlp_W2, mlp_b2,
        (float*)d_out);
}

// round 10
// speedup vs baseline: 2.8109x; 1.0885x over previous
#include <cuda_runtime.h>

#define NBATCH 256
#define NTOK   4096
#define NS     8
#define DD     64
#define SCALEF 0.125f
#define EPSA   1e-8f
#define NTILE  64
#define TILES  (NTOK / NTILE)

// ---- dynamic shared layout (float offsets) ----
#define O_SL    0          // slots [8][64]
#define O_QP    512        // raw q' = SCALE*Wk^T q [8][64]
#define O_QG    1024       // qgamma padded [8][68]
#define O_QC    1568       // qc [8]
#define O_DINV  1576       // 1/den [8]
#define O_TI    1584       // t_i [8]
#define O_QGS   1592       // sum qg [8]
#define O_QB    1600       // qb [8]
#define O_KL    1608       // kl [8]
#define O_GSH   1616       // ni gamma [64]
#define O_BSH   1680       // ni beta [64]
#define O_NPG   1744       // npf gamma [64]
#define O_NPB   1808       // npf beta [64]
#define O_PRIOR 1872       // prior [8][128]
#define O_NUM   2896       // normalized updates pre-Wv [8][64]
#define O_SCR   3408
// attention scratch
#define O_KT0   (O_SCR)            // [64][68]
#define O_KT1   (O_SCR + 4352)
#define O_WT2   (O_SCR + 8704)     // w' [64][8]  (also qtmp)
#define O_RED   (O_SCR + 9216)     // acc partials [512][8]
#define O_WR    (O_SCR + 13312)    // W partials [64][8]
#define O_TR    (O_SCR + 13824)    // t partials [64][8]  -> ends at O_SCR+14336
// update scratch (aliases KT region)
#define O_U     (O_SCR)
#define O_GI    (O_SCR + 512)
#define O_GH    (O_SCR + 2048)
#define O_HN    (O_SCR + 3584)
#define O_LNX   (O_SCR + 4096)
#define O_HID   (O_SCR + 4608)
#define O_PH    (O_SCR + 5632)
#define O_POST  (O_SCR + 6656)
// init scratch
#define O_P0    (O_SCR)
#define O_PHI   (O_SCR + 512)
#define O_T2    (O_SCR + 1536)

#define SMEM_FLOATS 17760          // >= O_SCR + 14336 = 17744 (was 17728: OVERFLOW)
#define SMEM_BYTES  (SMEM_FLOATS * 4)

__device__ __forceinline__ void cp16(float* smem_dst, const float* gsrc) {
    unsigned dst = (unsigned)__cvta_generic_to_shared(smem_dst);
    asm volatile("cp.async.cg.shared.global [%0], [%1], 16;\n" :: "r"(dst), "l"(gsrc));
}
__device__ __forceinline__ void cp_commit() { asm volatile("cp.async.commit_group;\n"); }
__device__ __forceinline__ float sigmoidf_(float x) { return 1.0f / (1.0f + expf(-x)); }

__global__ __launch_bounds__(512, 2) void mega_kernel(
    const float* __restrict__ inputs,
    const float* __restrict__ slots_in,
    const float* __restrict__ prior_slots,
    const float* __restrict__ eps_noise,
    const float* __restrict__ ni_g,  const float* __restrict__ ni_b,
    const float* __restrict__ npf_g, const float* __restrict__ npf_b,
    const float* __restrict__ Wq, const float* __restrict__ bq,
    const float* __restrict__ Wk, const float* __restrict__ bk,
    const float* __restrict__ Wv, const float* __restrict__ bv,
    const float* __restrict__ sr_W1, const float* __restrict__ sr_b1,
    const float* __restrict__ sr_W2, const float* __restrict__ sr_b2,
    const float* __restrict__ pr_W1, const float* __restrict__ pr_b1,
    const float* __restrict__ pr_W2, const float* __restrict__ pr_b2,
    const float* __restrict__ gru_Wih, const float* __restrict__ gru_Whh,
    const float* __restrict__ gru_bih, const float* __restrict__ gru_bhh,
    const float* __restrict__ mlp_W1, const float* __restrict__ mlp_b1,
    const float* __restrict__ mlp_W2, const float* __restrict__ mlp_b2,
    float* __restrict__ out)
{
    extern __shared__ float sm[];
    const int b = blockIdx.x;
    const int t = threadIdx.x;

    float* SLs    = sm + O_SL;
    float* PRIORs = sm + O_PRIOR;
    float* KLs    = sm + O_KL;

    // ---------------- init ----------------
    {
        SLs[t]         = slots_in[(long)b * 512 + t];
        (sm + O_P0)[t] = prior_slots[(long)b * 512 + t];
        if (t < 64) {
            (sm + O_GSH)[t] = ni_g[t];  (sm + O_BSH)[t] = ni_b[t];
            (sm + O_NPG)[t] = npf_g[t]; (sm + O_NPB)[t] = npf_b[t];
        }
        if (t < 8) KLs[t] = 0.f;
        __syncthreads();
        {
            int m = t & 127, ip = t >> 7, i0 = ip * 2;
            float ax = 0.f, ay = 0.f;
            const float* wr = pr_W1 + m * 64;
            #pragma unroll 8
            for (int d = 0; d < 64; ++d) {
                float w = __ldg(wr + d);
                ax += (sm + O_P0)[i0 * 64 + d] * w;
                ay += (sm + O_P0)[(i0 + 1) * 64 + d] * w;
            }
            float b1 = __ldg(pr_b1 + m);
            (sm + O_PHI)[i0 * 128 + m]       = fmaxf(ax + b1, 0.f);
            (sm + O_PHI)[(i0 + 1) * 128 + m] = fmaxf(ay + b1, 0.f);
        }
        __syncthreads();
        {
            int m = t & 127, ip = t >> 7, i0 = ip * 2;
            float ax = 0.f, ay = 0.f;
            const float* wr = pr_W2 + m * 128;
            #pragma unroll 8
            for (int k = 0; k < 128; ++k) {
                float w = __ldg(wr + k);
                ax += (sm + O_PHI)[i0 * 128 + k] * w;
                ay += (sm + O_PHI)[(i0 + 1) * 128 + k] * w;
            }
            float b2 = __ldg(pr_b2 + m);
            PRIORs[i0 * 128 + m]       = ax + b2;
            PRIORs[(i0 + 1) * 128 + m] = ay + b2;
        }
        __syncthreads();
        {
            int m = t & 127, ip = t >> 7, i0 = ip * 2;
            float ax = 0.f, ay = 0.f;
            const float* wr = sr_W1 + m * 64;
            #pragma unroll 8
            for (int d = 0; d < 64; ++d) {
                float w = __ldg(wr + d);
                ax += SLs[i0 * 64 + d] * w;
                ay += SLs[(i0 + 1) * 64 + d] * w;
            }
            float b1 = __ldg(sr_b1 + m);
            (sm + O_PHI)[i0 * 128 + m]       = fmaxf(ax + b1, 0.f);
            (sm + O_PHI)[(i0 + 1) * 128 + m] = fmaxf(ay + b1, 0.f);
        }
        __syncthreads();
        {
            int m = t & 127, ip = t >> 7, i0 = ip * 2;
            float ax = 0.f, ay = 0.f;
            const float* wr = sr_W2 + m * 128;
            #pragma unroll 8
            for (int k = 0; k < 128; ++k) {
                float w = __ldg(wr + k);
                ax += (sm + O_PHI)[i0 * 128 + k] * w;
                ay += (sm + O_PHI)[(i0 + 1) * 128 + k] * w;
            }
            float b2 = __ldg(sr_b2 + m);
            (sm + O_T2)[i0 * 128 + m]       = ax + b2;
            (sm + O_T2)[(i0 + 1) * 128 + m] = ay + b2;
        }
        __syncthreads();
        {
            int i = t >> 6, d = t & 63;
            float mu = (sm + O_T2)[i * 128 + d];
            float lv = (sm + O_T2)[i * 128 + 64 + d];
            SLs[t] = eps_noise[(long)b * 512 + t] * expf(0.5f * lv) + mu;
        }
        __syncthreads();
    }

    // ---------------- iterations ----------------
    for (int iter = 0; iter < 3; ++iter) {
        // prefetch tile 0
        {
            const float* src = inputs + ((long)b * NTOK) * DD;
            float* kb = sm + O_KT0;
            int m0 = t, m1 = t + 512;
            cp16(kb + ((m0 >> 4) * 68 + (m0 & 15) * 4), src + m0 * 4);
            cp16(kb + ((m1 >> 4) * 68 + (m1 & 15) * 4), src + m1 * 4);
            cp_commit();
        }
        // q = slots@Wq^T + bq  -> qtmp (WT2 region)
        {
            int i = t >> 6, o = t & 63;
            float a = __ldg(bq + o);
            const float* wr = Wq + o * 64;
            #pragma unroll 8
            for (int d = 0; d < 64; ++d) a += SLs[i * 64 + d] * __ldg(wr + d);
            (sm + O_WT2)[i * 64 + o] = a;
        }
        __syncthreads();
        // QP = SCALE*Wk^T q ; QG = QP*gamma (padded); qc = SCALE*(q.bk)
        {
            int i = t >> 6, d = t & 63;
            float a = 0.f;
            #pragma unroll 8
            for (int o = 0; o < 64; ++o) a += (sm + O_WT2)[i * 64 + o] * __ldg(Wk + o * 64 + d);
            a *= SCALEF;
            (sm + O_QP)[i * 64 + d] = a;
            (sm + O_QG)[i * 68 + d] = a * (sm + O_GSH)[d];
        }
        if (t < 8) {
            float a = 0.f;
            #pragma unroll 8
            for (int o = 0; o < 64; ++o) a += (sm + O_WT2)[t * 64 + o] * __ldg(bk + o);
            (sm + O_QC)[t] = a * SCALEF;
        }
        __syncthreads();
        if (t < 8) {
            float s1 = 0.f, s2 = 0.f;
            #pragma unroll 8
            for (int d = 0; d < 64; ++d) {
                s1 += (sm + O_QG)[t * 68 + d];
                s2 += (sm + O_QP)[t * 64 + d] * (sm + O_BSH)[d];
            }
            (sm + O_QGS)[t] = s1;
            (sm + O_QB)[t]  = s2 + (sm + O_QC)[t];
        }
        __syncthreads();

        // per-thread state for the tile loop
        const int dj = t >> 3;      // token within tile (dots role)
        const int di = t & 7;       // slot (dots role)
        const int a_d8 = t & 7;     // float4 col (accum role)
        const int a_s  = ((t >> 5) & 1) * 4 + ((t >> 3) & 3);   // slot (accum role)
        const int a_jg = t >> 6;    // token group (accum role)
        float4 acc0 = {0.f,0.f,0.f,0.f}, acc1 = {0.f,0.f,0.f,0.f};
        float Wpart = 0.f, tpart = 0.f;

        for (int tt = 0; tt < TILES; ++tt) {
            float4* kt4 = (float4*)(sm + ((tt & 1) ? O_KT1 : O_KT0));
            if (tt < TILES - 1) {
                const float* src = inputs + ((long)b * NTOK + (long)(tt + 1) * NTILE) * DD;
                float* kb = sm + (((tt + 1) & 1) ? O_KT1 : O_KT0);
                int m0 = t, m1 = t + 512;
                cp16(kb + ((m0 >> 4) * 68 + (m0 & 15) * 4), src + m0 * 4);
                cp16(kb + ((m1 >> 4) * 68 + (m1 & 15) * 4), src + m1 * 4);
                cp_commit();
                asm volatile("cp.async.wait_group 1;\n");
            } else {
                asm volatile("cp.async.wait_group 0;\n");
            }
            __syncthreads();

            // ---- dots on RAW x (LN folded) ----
            {
                const float4* xrow = kt4 + dj * 17;
                const float4* qgr  = (const float4*)(sm + O_QG) + di * 17;
                float s = 0.f, ss = 0.f, dp = 0.f;
                #pragma unroll
                for (int dq = 0; dq < 16; ++dq) {
                    float4 x4 = xrow[dq];
                    float4 q4 = qgr[dq];
                    s  += (x4.x + x4.y) + (x4.z + x4.w);
                    ss += x4.x * x4.x + x4.y * x4.y + x4.z * x4.z + x4.w * x4.w;
                    dp += x4.x * q4.x + x4.y * q4.y + x4.z * q4.z + x4.w * q4.w;
                }
                float m = s * (1.f / 64.f);
                float var = ss * (1.f / 64.f) - m * m;
                float rstd = rsqrtf(var + 1e-5f);
                float dv = rstd * dp - m * rstd * (sm + O_QGS)[di] + (sm + O_QB)[di];
                // softmax over the 8 slot-lanes
                float mx = dv;
                mx = fmaxf(mx, __shfl_xor_sync(~0u, mx, 1));
                mx = fmaxf(mx, __shfl_xor_sync(~0u, mx, 2));
                mx = fmaxf(mx, __shfl_xor_sync(~0u, mx, 4));
                float e = __expf(dv - mx);
                float sum = e;
                sum += __shfl_xor_sync(~0u, sum, 1);
                sum += __shfl_xor_sync(~0u, sum, 2);
                sum += __shfl_xor_sync(~0u, sum, 4);
                float w = e / sum + EPSA;
                float wp = w * rstd;
                (sm + O_WT2)[dj * 8 + di] = wp;
                Wpart += w;
                tpart += wp * m;
            }
            __syncthreads();

            // ---- accumulate A = sum_j w'_ij * x_j (raw) ----
            #pragma unroll
            for (int k = 0; k < 8; ++k) {
                int j = a_jg * 8 + k;
                float wp = (sm + O_WT2)[j * 8 + a_s];
                float4 x0 = kt4[j * 17 + a_d8];
                float4 x1 = kt4[j * 17 + a_d8 + 8];
                acc0.x += wp * x0.x; acc0.y += wp * x0.y; acc0.z += wp * x0.z; acc0.w += wp * x0.w;
                acc1.x += wp * x1.x; acc1.y += wp * x1.y; acc1.z += wp * x1.z; acc1.w += wp * x1.w;
            }
            __syncthreads();
        }

        // ---- reductions ----
        {
            float4* myred = (float4*)(sm + O_RED + t * 8);
            myred[0] = acc0; myred[1] = acc1;
            (sm + O_WR)[dj * 8 + di] = Wpart;
            (sm + O_TR)[dj * 8 + di] = tpart;
        }
        __syncthreads();
        if (t < 8) {
            float den = 0.f, ti = 0.f;
            #pragma unroll 8
            for (int j = 0; j < 64; ++j) {
                den += (sm + O_WR)[j * 8 + t];
                ti  += (sm + O_TR)[j * 8 + t];
            }
            (sm + O_DINV)[t] = 1.0f / den;
            (sm + O_TI)[t]   = ti;
        }
        __syncthreads();
        // NUM[i][d] = (gamma_d*(A - t_i)) * dinv_i + beta_d
        {
            int i = t >> 6, d = t & 63;
            int d4 = d >> 2, e = d & 3;
            int c = d4 >> 3, d8r = d4 & 7;
            int sh = i >> 2, sl = i & 3;
            float A = 0.f;
            #pragma unroll
            for (int jg = 0; jg < 8; ++jg)
                A += (sm + O_RED)[(jg * 64 + sh * 32 + sl * 8 + d8r) * 8 + c * 4 + e];
            (sm + O_NUM)[i * 64 + d] =
                (sm + O_GSH)[d] * (A - (sm + O_TI)[i]) * (sm + O_DINV)[i] + (sm + O_BSH)[d];
        }
        __syncthreads();

        // ---- u = Wv @ NUM + bv ----
        {
            int i = t >> 6, o = t & 63;
            float a = 0.f;
            const float* wr = Wv + o * 64;
            #pragma unroll 8
            for (int d = 0; d < 64; ++d) a += (sm + O_NUM)[i * 64 + d] * __ldg(wr + d);
            (sm + O_U)[i * 64 + o] = a + __ldg(bv + o);
        }
        __syncthreads();

        // ---- GRU gates ----
        if (t < 384) {
            int o = (t < 192) ? t : t - 192;
            const float* wr = ((t < 192) ? gru_Wih : gru_Whh) + o * 64;
            const float* xr = (t < 192) ? (sm + O_U) : SLs;
            float a[NS];
            #pragma unroll
            for (int i = 0; i < NS; ++i) a[i] = 0.f;
            #pragma unroll 4
            for (int d = 0; d < 64; ++d) {
                float w = __ldg(wr + d);
                #pragma unroll
                for (int i = 0; i < NS; ++i) a[i] += xr[i * 64 + d] * w;
            }
            float bb = (t < 192) ? __ldg(gru_bih + o) : __ldg(gru_bhh + o);
            float* dst = (t < 192) ? (sm + O_GI) : (sm + O_GH);
            #pragma unroll
            for (int i = 0; i < NS; ++i) dst[i * 192 + o] = a[i] + bb;
        }
        __syncthreads();
        {
            int i = t >> 6, d = t & 63;
            float gi0 = (sm + O_GI)[i * 192 + d],       gh0 = (sm + O_GH)[i * 192 + d];
            float gi1 = (sm + O_GI)[i * 192 + 64 + d],  gh1 = (sm + O_GH)[i * 192 + 64 + d];
            float gi2 = (sm + O_GI)[i * 192 + 128 + d], gh2 = (sm + O_GH)[i * 192 + 128 + d];
            float rg = sigmoidf_(gi0 + gh0);
            float z  = sigmoidf_(gi1 + gh1);
            float n  = tanhf(gi2 + rg * gh2);
            (sm + O_HN)[t] = (1.f - z) * n + z * SLs[t];
        }
        __syncthreads();
        if (t < 256) {
            int i = t >> 5, lane = t & 31;
            float a = (sm + O_HN)[i * 64 + lane], b2 = (sm + O_HN)[i * 64 + lane + 32];
            float s = a + b2;
            #pragma unroll
            for (int off = 16; off > 0; off >>= 1) s += __shfl_xor_sync(~0u, s, off);
            float m = s * (1.f / 64.f);
            float e0 = a - m, e1 = b2 - m;
            float ss = e0 * e0 + e1 * e1;
            #pragma unroll
            for (int off = 16; off > 0; off >>= 1) ss += __shfl_xor_sync(~0u, ss, off);
            float rstd = rsqrtf(ss * (1.f / 64.f) + 1e-5f);
            (sm + O_LNX)[i * 64 + lane]      = e0 * rstd * (sm + O_NPG)[lane]      + (sm + O_NPB)[lane];
            (sm + O_LNX)[i * 64 + lane + 32] = e1 * rstd * (sm + O_NPG)[lane + 32] + (sm + O_NPB)[lane + 32];
        }
        __syncthreads();
        {
            int m = t & 127, ip = t >> 7, i0 = ip * 2;
            float ax = 0.f, ay = 0.f;
            const float* wr = mlp_W1 + m * 64;
            #pragma unroll 8
            for (int d = 0; d < 64; ++d) {
                float w = __ldg(wr + d);
                ax += (sm + O_LNX)[i0 * 64 + d] * w;
                ay += (sm + O_LNX)[(i0 + 1) * 64 + d] * w;
            }
            float b1 = __ldg(mlp_b1 + m);
            (sm + O_HID)[i0 * 128 + m]       = fmaxf(ax + b1, 0.f);
            (sm + O_HID)[(i0 + 1) * 128 + m] = fmaxf(ay + b1, 0.f);
        }
        __syncthreads();
        {
            int i = t >> 6, d = t & 63;
            float a = 0.f;
            const float* wr = mlp_W2 + d * 128;
            #pragma unroll 8
            for (int k = 0; k < 128; ++k) a += (sm + O_HID)[i * 128 + k] * __ldg(wr + k);
            SLs[t] = (sm + O_HN)[t] + a + __ldg(mlp_b2 + d);
        }
        __syncthreads();
        {
            int m = t & 127, ip = t >> 7, i0 = ip * 2;
            float ax = 0.f, ay = 0.f;
            const float* wr = sr_W1 + m * 64;
            #pragma unroll 8
            for (int d = 0; d < 64; ++d) {
                float w = __ldg(wr + d);
                ax += SLs[i0 * 64 + d] * w;
                ay += SLs[(i0 + 1) * 64 + d] * w;
            }
            float b1 = __ldg(sr_b1 + m);
            (sm + O_PH)[i0 * 128 + m]       = fmaxf(ax + b1, 0.f);
            (sm + O_PH)[(i0 + 1) * 128 + m] = fmaxf(ay + b1, 0.f);
        }
        __syncthreads();
        {
            int m = t & 127, ip = t >> 7, i0 = ip * 2;
            float ax = 0.f, ay = 0.f;
            const float* wr = sr_W2 + m * 128;
            #pragma unroll 8
            for (int k = 0; k < 128; ++k) {
                float w = __ldg(wr + k);
                ax += (sm + O_PH)[i0 * 128 + k] * w;
                ay += (sm + O_PH)[(i0 + 1) * 128 + k] * w;
            }
            float b2 = __ldg(sr_b2 + m);
            (sm + O_POST)[i0 * 128 + m]       = ax + b2;
            (sm + O_POST)[(i0 + 1) * 128 + m] = ay + b2;
        }
        __syncthreads();
        if (t < 256) {
            int i = t >> 5, lane = t & 31;
            float term = 0.f;
            #pragma unroll
            for (int q = 0; q < 2; ++q) {
                int d = lane + q * 32;
                float m_po = (sm + O_POST)[i * 128 + d];
                float lv_po = (sm + O_POST)[i * 128 + 64 + d];
                float m_pr = PRIORs[i * 128 + d];
                float lv_pr = PRIORs[i * 128 + 64 + d];
                float dm = m_po - m_pr;
                term += lv_pr - lv_po + (expf(lv_po) + dm * dm) * expf(-lv_pr) - 1.0f;
            }
            #pragma unroll
            for (int off = 16; off > 0; off >>= 1) term += __shfl_xor_sync(~0u, term, off);
            if (lane == 0) KLs[i] += 0.5f * term;
        }
        __syncthreads();
    }

    out[(long)b * 512 + t] = SLs[t];
    if (t < 8) out[131072 + b * 8 + t] = KLs[t];
}

extern "C" void kernel_launch(void* const* d_in, const int* in_sizes, int n_in,
                              void* d_out, int out_size)
{
    const float* inputs      = (const float*)d_in[0];
    const float* slots       = (const float*)d_in[1];
    const float* prior_slots = (const float*)d_in[2];
    const float* eps_noise   = (const float*)d_in[3];
    const float* ni_g  = (const float*)d_in[4];
    const float* ni_b  = (const float*)d_in[5];
    const float* npf_g = (const float*)d_in[6];
    const float* npf_b = (const float*)d_in[7];
    const float* Wq = (const float*)d_in[8];
    const float* bq = (const float*)d_in[9];
    const float* Wk = (const float*)d_in[10];
    const float* bk = (const float*)d_in[11];
    const float* Wv = (const float*)d_in[12];
    const float* bv = (const float*)d_in[13];
    const float* sr_W1 = (const float*)d_in[14];
    const float* sr_b1 = (const float*)d_in[15];
    const float* sr_W2 = (const float*)d_in[16];
    const float* sr_b2 = (const float*)d_in[17];
    const float* pr_W1 = (const float*)d_in[18];
    const float* pr_b1 = (const float*)d_in[19];
    const float* pr_W2 = (const float*)d_in[20];
    const float* pr_b2 = (const float*)d_in[21];
    const float* gru_Wih = (const float*)d_in[22];
    const float* gru_Whh = (const float*)d_in[23];
    const float* gru_bih = (const float*)d_in[24];
    const float* gru_bhh = (const float*)d_in[25];
    const float* mlp_W1 = (const float*)d_in[26];
    const float* mlp_b1 = (const float*)d_in[27];
    const float* mlp_W2 = (const float*)d_in[28];
    const float* mlp_b2 = (const float*)d_in[29];

    cudaFuncSetAttribute(mega_kernel, cudaFuncAttributeMaxDynamicSharedMemorySize, SMEM_BYTES);

    mega_kernel<<<NBATCH, 512, SMEM_BYTES>>>(
        inputs, slots, prior_slots, eps_noise,
        ni_g, ni_b, npf_g, npf_b,
        Wq, bq, Wk, bk, Wv, bv,
        sr_W1, sr_b1, sr_W2, sr_b2,
        pr_W1, pr_b1, pr_W2, pr_b2,
        gru_Wih, gru_Whh, gru_bih, gru_bhh,
        mlp_W1, mlp_b1, mlp_W2, mlp_b2,
        (float*)d_out);
}

// round 12
// speedup vs baseline: 3.1795x; 1.1311x over previous
#include <cuda_runtime.h>

#define NBATCH 256
#define NTOK   4096
#define NS     8
#define SCALEF 0.125f
#define EPSA   1e-8f

// ---------------- global scratch ----------------
__device__ float g_slots[NBATCH * 512];
__device__ float g_prior[NBATCH * 1024];
__device__ float g_kl[NBATCH * 8];
__device__ float g_qg[NBATCH * 512];     // SCALE*(Wk^T q)*gamma
__device__ float g_qgs[NBATCH * 8];      // sum_d qg
__device__ float g_qb[NBATCH * 8];       // qp.beta + qc
__device__ float g_pA[NBATCH * 8 * 8 * 64];  // per-chunk A partials
__device__ float g_pW[NBATCH * 8 * 8];
__device__ float g_pT[NBATCH * 8 * 8];

__device__ __forceinline__ void cp16(float* smem_dst, const float* gsrc) {
    unsigned dst = (unsigned)__cvta_generic_to_shared(smem_dst);
    asm volatile("cp.async.cg.shared.global [%0], [%1], 16;\n" :: "r"(dst), "l"(gsrc));
}
__device__ __forceinline__ void cp_commit() { asm volatile("cp.async.commit_group;\n"); }
__device__ __forceinline__ float sigmoidf_(float x) { return 1.0f / (1.0f + expf(-x)); }

// =======================================================================
// ATTENTION: 2048 blocks (batch x 8 chunks) x 256 threads, 8 tiles each
// =======================================================================
#define AQ_QG  0          // [8][68] padded
#define AQ_QGS 544
#define AQ_QB  552
#define AQ_WT2 560        // w' [64][8]
#define AQ_WR  1072       // [32][8]
#define AQ_TR  1328       // [32][8]
#define AQ_RED 1584       // [256][8]
#define AQ_KT0 3632       // [64][68]
#define AQ_KT1 7984
#define AQ_TOT 12336
#define AQ_BYTES (AQ_TOT * 4)

__global__ __launch_bounds__(256, 4) void attn_kernel(const float* __restrict__ inputs)
{
    extern __shared__ float sm[];
    const int blk = blockIdx.x;
    const int b = blk >> 3, chunk = blk & 7;
    const int t = threadIdx.x;

    for (int e = t; e < 512; e += 256)
        sm[AQ_QG + (e >> 6) * 68 + (e & 63)] = g_qg[b * 512 + e];
    if (t < 8) { sm[AQ_QGS + t] = g_qgs[b * 8 + t]; sm[AQ_QB + t] = g_qb[b * 8 + t]; }

    const float* base = inputs + ((long)b * NTOK + chunk * 512) * 64;
    {   // prefetch tile 0
        float* kb = sm + AQ_KT0;
        #pragma unroll
        for (int k2 = 0; k2 < 4; ++k2) {
            int m = t + k2 * 256;
            cp16(kb + (m >> 4) * 68 + (m & 15) * 4, base + m * 4);
        }
        cp_commit();
    }
    __syncthreads();

    const int dj0 = t >> 3, di = t & 7;
    const int a_d8 = t & 7, a_s = (t >> 3) & 7, a_jg = t >> 6;
    float4 acc0 = {0.f,0.f,0.f,0.f}, acc1 = {0.f,0.f,0.f,0.f};
    float Wpart = 0.f, tpart = 0.f;
    const float qgs = sm[AQ_QGS + di];
    const float qb  = sm[AQ_QB + di];
    const float4* qgr = (const float4*)(sm + AQ_QG) + di * 17;

    for (int tt = 0; tt < 8; ++tt) {
        float4* kt4 = (float4*)(sm + ((tt & 1) ? AQ_KT1 : AQ_KT0));
        if (tt < 7) {
            const float* src = base + (tt + 1) * 64 * 64;
            float* kb = sm + (((tt + 1) & 1) ? AQ_KT1 : AQ_KT0);
            #pragma unroll
            for (int k2 = 0; k2 < 4; ++k2) {
                int m = t + k2 * 256;
                cp16(kb + (m >> 4) * 68 + (m & 15) * 4, src + m * 4);
            }
            cp_commit();
            asm volatile("cp.async.wait_group 1;\n");
        } else {
            asm volatile("cp.async.wait_group 0;\n");
        }
        __syncthreads();

        // ---- dots (LN folded), 2 tokens per thread ----
        #pragma unroll
        for (int rep = 0; rep < 2; ++rep) {
            int dj = dj0 + rep * 32;
            const float4* xrow = kt4 + dj * 17;
            float s = 0.f, ss = 0.f, dp = 0.f;
            #pragma unroll
            for (int dq = 0; dq < 16; ++dq) {
                float4 x4 = xrow[dq];
                float4 q4 = qgr[dq];
                s  += (x4.x + x4.y) + (x4.z + x4.w);
                ss += x4.x * x4.x + x4.y * x4.y + x4.z * x4.z + x4.w * x4.w;
                dp += x4.x * q4.x + x4.y * q4.y + x4.z * q4.z + x4.w * q4.w;
            }
            float m = s * (1.f / 64.f);
            float var = ss * (1.f / 64.f) - m * m;
            float rstd = rsqrtf(var + 1e-5f);
            float dv = rstd * dp - m * rstd * qgs + qb;
            float mx = dv;
            mx = fmaxf(mx, __shfl_xor_sync(~0u, mx, 1));
            mx = fmaxf(mx, __shfl_xor_sync(~0u, mx, 2));
            mx = fmaxf(mx, __shfl_xor_sync(~0u, mx, 4));
            float e = __expf(dv - mx);
            float sum = e;
            sum += __shfl_xor_sync(~0u, sum, 1);
            sum += __shfl_xor_sync(~0u, sum, 2);
            sum += __shfl_xor_sync(~0u, sum, 4);
            float w = e / sum + EPSA;
            float wp = w * rstd;
            sm[AQ_WT2 + dj * 8 + di] = wp;
            Wpart += w;
            tpart += wp * m;
        }
        __syncthreads();

        // ---- accumulate A = sum_j w'_ij x_j ----
        #pragma unroll 4
        for (int k = 0; k < 16; ++k) {
            int j = a_jg * 16 + k;
            float wp = sm[AQ_WT2 + j * 8 + a_s];
            float4 x0 = kt4[j * 17 + a_d8];
            float4 x1 = kt4[j * 17 + a_d8 + 8];
            acc0.x += wp * x0.x; acc0.y += wp * x0.y; acc0.z += wp * x0.z; acc0.w += wp * x0.w;
            acc1.x += wp * x1.x; acc1.y += wp * x1.y; acc1.z += wp * x1.z; acc1.w += wp * x1.w;
        }
        __syncthreads();
    }

    ((float4*)(sm + AQ_RED))[t * 2]     = acc0;
    ((float4*)(sm + AQ_RED))[t * 2 + 1] = acc1;
    sm[AQ_WR + dj0 * 8 + di] = Wpart;
    sm[AQ_TR + dj0 * 8 + di] = tpart;
    __syncthreads();
    for (int e = t; e < 512; e += 256) {
        int i = e >> 6, d = e & 63;
        int d4 = d >> 2, c = d4 >> 3, d8r = d4 & 7, ee = d & 3;
        float A = 0.f;
        #pragma unroll
        for (int jg = 0; jg < 4; ++jg)
            A += sm[AQ_RED + (jg * 64 + i * 8 + d8r) * 8 + c * 4 + ee];
        g_pA[((b * 8 + chunk) * 8 + i) * 64 + d] = A;
    }
    if (t < 8) {
        float w = 0.f, ti = 0.f;
        #pragma unroll
        for (int j = 0; j < 32; ++j) { w += sm[AQ_WR + j * 8 + t]; ti += sm[AQ_TR + j * 8 + t]; }
        g_pW[(b * 8 + chunk) * 8 + t] = w;
        g_pT[(b * 8 + chunk) * 8 + t] = ti;
    }
}

// =======================================================================
// INIT: 256 blocks x 256 threads
// =======================================================================
__global__ __launch_bounds__(256) void init_kernel(
    const float* __restrict__ slots_in, const float* __restrict__ prior_slots,
    const float* __restrict__ eps_noise,
    const float* __restrict__ ni_g, const float* __restrict__ ni_b,
    const float* __restrict__ sr_W1, const float* __restrict__ sr_b1,
    const float* __restrict__ sr_W2, const float* __restrict__ sr_b2,
    const float* __restrict__ pr_W1, const float* __restrict__ pr_b1,
    const float* __restrict__ pr_W2, const float* __restrict__ pr_b2,
    const float* __restrict__ Wq, const float* __restrict__ bq,
    const float* __restrict__ Wk, const float* __restrict__ bk)
{
    __shared__ float SL[512], P0[512], PHI[1024], T2[1024], QT[512], QP[512];
    __shared__ float GSH[64], BSH[64];
    const int b = blockIdx.x, t = threadIdx.x;

    for (int e = t; e < 512; e += 256) {
        SL[e] = slots_in[(long)b * 512 + e];
        P0[e] = prior_slots[(long)b * 512 + e];
    }
    if (t < 64) { GSH[t] = ni_g[t]; BSH[t] = ni_b[t]; }
    if (t < 8) g_kl[b * 8 + t] = 0.f;
    __syncthreads();
    // prior MLP
    {
        int m = t & 127, i0 = (t >> 7) * 4;
        float a[4] = {0.f,0.f,0.f,0.f};
        const float* wr = pr_W1 + m * 64;
        #pragma unroll 8
        for (int d = 0; d < 64; ++d) {
            float w = __ldg(wr + d);
            #pragma unroll
            for (int r = 0; r < 4; ++r) a[r] += P0[(i0 + r) * 64 + d] * w;
        }
        float b1 = __ldg(pr_b1 + m);
        #pragma unroll
        for (int r = 0; r < 4; ++r) PHI[(i0 + r) * 128 + m] = fmaxf(a[r] + b1, 0.f);
    }
    __syncthreads();
    {
        int m = t & 127, i0 = (t >> 7) * 4;
        float a[4] = {0.f,0.f,0.f,0.f};
        const float* wr = pr_W2 + m * 128;
        #pragma unroll 8
        for (int k = 0; k < 128; ++k) {
            float w = __ldg(wr + k);
            #pragma unroll
            for (int r = 0; r < 4; ++r) a[r] += PHI[(i0 + r) * 128 + k] * w;
        }
        float b2 = __ldg(pr_b2 + m);
        #pragma unroll
        for (int r = 0; r < 4; ++r) g_prior[(long)b * 1024 + (i0 + r) * 128 + m] = a[r] + b2;
    }
    __syncthreads();
    // posterior on initial slots
    {
        int m = t & 127, i0 = (t >> 7) * 4;
        float a[4] = {0.f,0.f,0.f,0.f};
        const float* wr = sr_W1 + m * 64;
        #pragma unroll 8
        for (int d = 0; d < 64; ++d) {
            float w = __ldg(wr + d);
            #pragma unroll
            for (int r = 0; r < 4; ++r) a[r] += SL[(i0 + r) * 64 + d] * w;
        }
        float b1 = __ldg(sr_b1 + m);
        #pragma unroll
        for (int r = 0; r < 4; ++r) PHI[(i0 + r) * 128 + m] = fmaxf(a[r] + b1, 0.f);
    }
    __syncthreads();
    {
        int m = t & 127, i0 = (t >> 7) * 4;
        float a[4] = {0.f,0.f,0.f,0.f};
        const float* wr = sr_W2 + m * 128;
        #pragma unroll 8
        for (int k = 0; k < 128; ++k) {
            float w = __ldg(wr + k);
            #pragma unroll
            for (int r = 0; r < 4; ++r) a[r] += PHI[(i0 + r) * 128 + k] * w;
        }
        float b2 = __ldg(sr_b2 + m);
        #pragma unroll
        for (int r = 0; r < 4; ++r) T2[(i0 + r) * 128 + m] = a[r] + b2;
    }
    __syncthreads();
    for (int e = t; e < 512; e += 256) {
        int i = e >> 6, d = e & 63;
        float mu = T2[i * 128 + d], lv = T2[i * 128 + 64 + d];
        float v = eps_noise[(long)b * 512 + e] * expf(0.5f * lv) + mu;
        SL[e] = v;
        g_slots[(long)b * 512 + e] = v;
    }
    __syncthreads();
    // q projection for iter 0
    for (int e = t; e < 512; e += 256) {
        int i = e >> 6, o = e & 63;
        float a = __ldg(bq + o);
        const float* wr = Wq + o * 64;
        #pragma unroll 8
        for (int d = 0; d < 64; ++d) a += SL[i * 64 + d] * __ldg(wr + d);
        QT[e] = a;
    }
    __syncthreads();
    for (int e = t; e < 512; e += 256) {
        int i = e >> 6, d = e & 63;
        float a = 0.f;
        #pragma unroll 8
        for (int o = 0; o < 64; ++o) a += QT[i * 64 + o] * __ldg(Wk + o * 64 + d);
        a *= SCALEF;
        QP[e] = a;
        g_qg[(long)b * 512 + e] = a * GSH[d];
    }
    __syncthreads();
    if (t < 8) {
        float s1 = 0.f, s2 = 0.f, qc = 0.f;
        #pragma unroll 8
        for (int d = 0; d < 64; ++d) {
            s1 += QP[t * 64 + d] * GSH[d];
            s2 += QP[t * 64 + d] * BSH[d];
            qc += QT[t * 64 + d] * __ldg(bk + d);
        }
        g_qgs[b * 8 + t] = s1;
        g_qb[b * 8 + t]  = s2 + qc * SCALEF;
    }
}

// =======================================================================
// UPDATE: 256 blocks x 256 threads
// =======================================================================
__global__ __launch_bounds__(256) void update_kernel(
    const float* __restrict__ Wv, const float* __restrict__ bv,
    const float* __restrict__ gru_Wih, const float* __restrict__ gru_Whh,
    const float* __restrict__ gru_bih, const float* __restrict__ gru_bhh,
    const float* __restrict__ npf_g, const float* __restrict__ npf_b,
    const float* __restrict__ mlp_W1, const float* __restrict__ mlp_b1,
    const float* __restrict__ mlp_W2, const float* __restrict__ mlp_b2,
    const float* __restrict__ sr_W1, const float* __restrict__ sr_b1,
    const float* __restrict__ sr_W2, const float* __restrict__ sr_b2,
    const float* __restrict__ ni_g, const float* __restrict__ ni_b,
    const float* __restrict__ Wq, const float* __restrict__ bq,
    const float* __restrict__ Wk, const float* __restrict__ bk,
    int final_iter, float* __restrict__ out)
{
    __shared__ float SL[512], NUMs[512], U[512];
    __shared__ float GI[1536], GH[1536];
    __shared__ float HN[512], LNX[512];
    __shared__ float HID[1024], PH[1024], POST[1024], PRI[1024];
    __shared__ float GSH[64], BSH[64], NPG[64], NPB[64];
    __shared__ float DINV[8], TI[8];
    __shared__ float QT[512], QP[512];
    const int b = blockIdx.x, t = threadIdx.x;

    for (int e = t; e < 512; e += 256) SL[e] = g_slots[(long)b * 512 + e];
    for (int e = t; e < 1024; e += 256) PRI[e] = g_prior[(long)b * 1024 + e];
    if (t < 64) { GSH[t] = ni_g[t]; BSH[t] = ni_b[t]; NPG[t] = npf_g[t]; NPB[t] = npf_b[t]; }
    if (t < 8) {
        float den = 0.f, ti = 0.f;
        #pragma unroll
        for (int c = 0; c < 8; ++c) {
            den += g_pW[(b * 8 + c) * 8 + t];
            ti  += g_pT[(b * 8 + c) * 8 + t];
        }
        DINV[t] = 1.0f / den;
        TI[t]   = ti;
    }
    __syncthreads();
    // NUM = gamma*(A - t_i)*dinv + beta
    for (int e = t; e < 512; e += 256) {
        int i = e >> 6, d = e & 63;
        float A = 0.f;
        #pragma unroll
        for (int c = 0; c < 8; ++c) A += g_pA[((b * 8 + c) * 8 + i) * 64 + d];
        NUMs[e] = GSH[d] * (A - TI[i]) * DINV[i] + BSH[d];
    }
    __syncthreads();
    // u = Wv @ NUM + bv
    for (int e = t; e < 512; e += 256) {
        int i = e >> 6, o = e & 63;
        float a = 0.f;
        const float* wr = Wv + o * 64;
        #pragma unroll 8
        for (int d = 0; d < 64; ++d) a += NUMs[i * 64 + d] * __ldg(wr + d);
        U[e] = a + __ldg(bv + o);
    }
    __syncthreads();
    // GRU gates (t<192 computes both gi and gh for row t)
    if (t < 192) {
        float ai[8], ah[8];
        #pragma unroll
        for (int i = 0; i < 8; ++i) { ai[i] = 0.f; ah[i] = 0.f; }
        const float* wi = gru_Wih + t * 64;
        const float* wh = gru_Whh + t * 64;
        #pragma unroll 4
        for (int d = 0; d < 64; ++d) {
            float wiv = __ldg(wi + d), whv = __ldg(wh + d);
            #pragma unroll
            for (int i = 0; i < 8; ++i) { ai[i] += U[i * 64 + d] * wiv; ah[i] += SL[i * 64 + d] * whv; }
        }
        float bi = __ldg(gru_bih + t), bh = __ldg(gru_bhh + t);
        #pragma unroll
        for (int i = 0; i < 8; ++i) { GI[i * 192 + t] = ai[i] + bi; GH[i * 192 + t] = ah[i] + bh; }
    }
    __syncthreads();
    for (int e = t; e < 512; e += 256) {
        int i = e >> 6, d = e & 63;
        float rg = sigmoidf_(GI[i * 192 + d] + GH[i * 192 + d]);
        float z  = sigmoidf_(GI[i * 192 + 64 + d] + GH[i * 192 + 64 + d]);
        float n  = tanhf(GI[i * 192 + 128 + d] + rg * GH[i * 192 + 128 + d]);
        HN[e] = (1.f - z) * n + z * SL[e];
    }
    __syncthreads();
    {   // LN(hn)
        int i = t >> 5, lane = t & 31;
        float a = HN[i * 64 + lane], b2 = HN[i * 64 + lane + 32];
        float s = a + b2;
        #pragma unroll
        for (int off = 16; off > 0; off >>= 1) s += __shfl_xor_sync(~0u, s, off);
        float m = s * (1.f / 64.f);
        float e0 = a - m, e1 = b2 - m;
        float ss = e0 * e0 + e1 * e1;
        #pragma unroll
        for (int off = 16; off > 0; off >>= 1) ss += __shfl_xor_sync(~0u, ss, off);
        float rstd = rsqrtf(ss * (1.f / 64.f) + 1e-5f);
        LNX[i * 64 + lane]      = e0 * rstd * NPG[lane]      + NPB[lane];
        LNX[i * 64 + lane + 32] = e1 * rstd * NPG[lane + 32] + NPB[lane + 32];
    }
    __syncthreads();
    {   // mlp hidden
        int m = t & 127, i0 = (t >> 7) * 4;
        float a[4] = {0.f,0.f,0.f,0.f};
        const float* wr = mlp_W1 + m * 64;
        #pragma unroll 8
        for (int d = 0; d < 64; ++d) {
            float w = __ldg(wr + d);
            #pragma unroll
            for (int r = 0; r < 4; ++r) a[r] += LNX[(i0 + r) * 64 + d] * w;
        }
        float b1 = __ldg(mlp_b1 + m);
        #pragma unroll
        for (int r = 0; r < 4; ++r) HID[(i0 + r) * 128 + m] = fmaxf(a[r] + b1, 0.f);
    }
    __syncthreads();
    // mlp out + residual -> new slots
    for (int e = t; e < 512; e += 256) {
        int i = e >> 6, d = e & 63;
        float a = 0.f;
        const float* wr = mlp_W2 + d * 128;
        #pragma unroll 8
        for (int k = 0; k < 128; ++k) a += HID[i * 128 + k] * __ldg(wr + k);
        float v = HN[e] + a + __ldg(mlp_b2 + d);
        SL[e] = v;
        g_slots[(long)b * 512 + e] = v;
    }
    __syncthreads();
    {   // posterior hidden
        int m = t & 127, i0 = (t >> 7) * 4;
        float a[4] = {0.f,0.f,0.f,0.f};
        const float* wr = sr_W1 + m * 64;
        #pragma unroll 8
        for (int d = 0; d < 64; ++d) {
            float w = __ldg(wr + d);
            #pragma unroll
            for (int r = 0; r < 4; ++r) a[r] += SL[(i0 + r) * 64 + d] * w;
        }
        float b1 = __ldg(sr_b1 + m);
        #pragma unroll
        for (int r = 0; r < 4; ++r) PH[(i0 + r) * 128 + m] = fmaxf(a[r] + b1, 0.f);
    }
    __syncthreads();
    {
        int m = t & 127, i0 = (t >> 7) * 4;
        float a[4] = {0.f,0.f,0.f,0.f};
        const float* wr = sr_W2 + m * 128;
        #pragma unroll 8
        for (int k = 0; k < 128; ++k) {
            float w = __ldg(wr + k);
            #pragma unroll
            for (int r = 0; r < 4; ++r) a[r] += PH[(i0 + r) * 128 + k] * w;
        }
        float b2 = __ldg(sr_b2 + m);
        #pragma unroll
        for (int r = 0; r < 4; ++r) POST[(i0 + r) * 128 + m] = a[r] + b2;
    }
    __syncthreads();
    {   // KL accumulate into g_kl
        int i = t >> 5, lane = t & 31;
        float term = 0.f;
        #pragma unroll
        for (int q = 0; q < 2; ++q) {
            int d = lane + q * 32;
            float m_po = POST[i * 128 + d], lv_po = POST[i * 128 + 64 + d];
            float m_pr = PRI[i * 128 + d],  lv_pr = PRI[i * 128 + 64 + d];
            float dm = m_po - m_pr;
            term += lv_pr - lv_po + (expf(lv_po) + dm * dm) * expf(-lv_pr) - 1.0f;
        }
        #pragma unroll
        for (int off = 16; off > 0; off >>= 1) term += __shfl_xor_sync(~0u, term, off);
        if (lane == 0) g_kl[b * 8 + i] += 0.5f * term;
    }
    __syncthreads();

    if (!final_iter) {
        // q projection for next iteration
        for (int e = t; e < 512; e += 256) {
            int i = e >> 6, o = e & 63;
            float a = __ldg(bq + o);
            const float* wr = Wq + o * 64;
            #pragma unroll 8
            for (int d = 0; d < 64; ++d) a += SL[i * 64 + d] * __ldg(wr + d);
            QT[e] = a;
        }
        __syncthreads();
        for (int e = t; e < 512; e += 256) {
            int i = e >> 6, d = e & 63;
            float a = 0.f;
            #pragma unroll 8
            for (int o = 0; o < 64; ++o) a += QT[i * 64 + o] * __ldg(Wk + o * 64 + d);
            a *= SCALEF;
            QP[e] = a;
            g_qg[(long)b * 512 + e] = a * GSH[d];
        }
        __syncthreads();
        if (t < 8) {
            float s1 = 0.f, s2 = 0.f, qc = 0.f;
            #pragma unroll 8
            for (int d = 0; d < 64; ++d) {
                s1 += QP[t * 64 + d] * GSH[d];
                s2 += QP[t * 64 + d] * BSH[d];
                qc += QT[t * 64 + d] * __ldg(bk + d);
            }
            g_qgs[b * 8 + t] = s1;
            g_qb[b * 8 + t]  = s2 + qc * SCALEF;
        }
    } else {
        for (int e = t; e < 512; e += 256) out[(long)b * 512 + e] = SL[e];
        if (t < 8) out[131072 + b * 8 + t] = g_kl[b * 8 + t];
    }
}

// =======================================================================
extern "C" void kernel_launch(void* const* d_in, const int* in_sizes, int n_in,
                              void* d_out, int out_size)
{
    const float* inputs      = (const float*)d_in[0];
    const float* slots       = (const float*)d_in[1];
    const float* prior_slots = (const float*)d_in[2];
    const float* eps_noise   = (const float*)d_in[3];
    const float* ni_g  = (const float*)d_in[4];
    const float* ni_b  = (const float*)d_in[5];
    const float* npf_g = (const float*)d_in[6];
    const float* npf_b = (const float*)d_in[7];
    const float* Wq = (const float*)d_in[8];
    const float* bq = (const float*)d_in[9];
    const float* Wk = (const float*)d_in[10];
    const float* bk = (const float*)d_in[11];
    const float* Wv = (const float*)d_in[12];
    const float* bv = (const float*)d_in[13];
    const float* sr_W1 = (const float*)d_in[14];
    const float* sr_b1 = (const float*)d_in[15];
    const float* sr_W2 = (const float*)d_in[16];
    const float* sr_b2 = (const float*)d_in[17];
    const float* pr_W1 = (const float*)d_in[18];
    const float* pr_b1 = (const float*)d_in[19];
    const float* pr_W2 = (const float*)d_in[20];
    const float* pr_b2 = (const float*)d_in[21];
    const float* gru_Wih = (const float*)d_in[22];
    const float* gru_Whh = (const float*)d_in[23];
    const float* gru_bih = (const float*)d_in[24];
    const float* gru_bhh = (const float*)d_in[25];
    const float* mlp_W1 = (const float*)d_in[26];
    const float* mlp_b1 = (const float*)d_in[27];
    const float* mlp_W2 = (const float*)d_in[28];
    const float* mlp_b2 = (const float*)d_in[29];

    cudaFuncSetAttribute(attn_kernel, cudaFuncAttributeMaxDynamicSharedMemorySize, AQ_BYTES);

    init_kernel<<<NBATCH, 256>>>(slots, prior_slots, eps_noise,
                                 ni_g, ni_b,
                                 sr_W1, sr_b1, sr_W2, sr_b2,
                                 pr_W1, pr_b1, pr_W2, pr_b2,
                                 Wq, bq, Wk, bk);
    for (int it = 0; it < 3; ++it) {
        attn_kernel<<<NBATCH * 8, 256, AQ_BYTES>>>(inputs);
        update_kernel<<<NBATCH, 256>>>(Wv, bv,
                                       gru_Wih, gru_Whh, gru_bih, gru_bhh,
                                       npf_g, npf_b,
                                       mlp_W1, mlp_b1, mlp_W2, mlp_b2,
                                       sr_W1, sr_b1, sr_W2, sr_b2,
                                       ni_g, ni_b, Wq, bq, Wk, bk,
                                       it == 2 ? 1 : 0, (float*)d_out);
    }
}

// round 13
// speedup vs baseline: 4.1323x; 1.2997x over previous
#include <cuda_runtime.h>

#define NBATCH 256
#define NTOK   4096
#define NS     8
#define SCALEF 0.125f
#define EPSA   1e-8f

// ---------------- global scratch ----------------
__device__ float g_slots[NBATCH * 512];
__device__ float g_prior[NBATCH * 1024];
__device__ float g_kl[NBATCH * 8];
__device__ float g_qg[NBATCH * 512];
__device__ float g_qgs[NBATCH * 8];
__device__ float g_qb[NBATCH * 8];
__device__ float g_pA[NBATCH * 8 * 8 * 64];
__device__ float g_pW[NBATCH * 8 * 8];
__device__ float g_pT[NBATCH * 8 * 8];

__device__ __forceinline__ void cp16(float* smem_dst, const float* gsrc) {
    unsigned dst = (unsigned)__cvta_generic_to_shared(smem_dst);
    asm volatile("cp.async.cg.shared.global [%0], [%1], 16;\n" :: "r"(dst), "l"(gsrc));
}
__device__ __forceinline__ void cp_commit() { asm volatile("cp.async.commit_group;\n"); }
__device__ __forceinline__ float sigmoidf_(float x) { return 1.0f / (1.0f + expf(-x)); }

// 64-thread block dual reduction (deterministic)
__device__ __forceinline__ void red64x2(float& a, float& b, float* scr, int t) {
    #pragma unroll
    for (int off = 16; off > 0; off >>= 1) {
        a += __shfl_xor_sync(0xffffffffu, a, off);
        b += __shfl_xor_sync(0xffffffffu, b, off);
    }
    __syncthreads();
    if ((t & 31) == 0) { scr[(t >> 5) * 2] = a; scr[(t >> 5) * 2 + 1] = b; }
    __syncthreads();
    a = scr[0] + scr[2];
    b = scr[1] + scr[3];
}

// =======================================================================
// ATTENTION: 2048 blocks (batch x 8 chunks) x 256 threads
// =======================================================================
#define AQ_QG  0           // [8][68]
#define AQ_QGS 544
#define AQ_QB  552
#define AQ_WT2 560         // [64][8]
#define AQ_WR  1072        // [64][8]
#define AQ_TR  1584        // [64][8]
#define AQ_KT0 2096        // [64][68]
#define AQ_KT1 6448
#define AQ_RED AQ_KT0      // alias: final accum uses KT1, RED safe after barrier
#define AQ_TOT 10800
#define AQ_BYTES (AQ_TOT * 4)

__global__ __launch_bounds__(256, 4) void attn_kernel(const float* __restrict__ inputs)
{
    extern __shared__ float sm[];
    const int blk = blockIdx.x;
    const int b = blk >> 3, chunk = blk & 7;
    const int t = threadIdx.x;

    for (int e = t; e < 512; e += 256)
        sm[AQ_QG + (e >> 6) * 68 + (e & 63)] = g_qg[b * 512 + e];
    if (t < 8) { sm[AQ_QGS + t] = g_qgs[b * 8 + t]; sm[AQ_QB + t] = g_qb[b * 8 + t]; }

    const float* base = inputs + ((long)b * NTOK + chunk * 512) * 64;
    {
        float* kb = sm + AQ_KT0;
        #pragma unroll
        for (int k2 = 0; k2 < 4; ++k2) {
            int m = t + k2 * 256;
            cp16(kb + (m >> 4) * 68 + (m & 15) * 4, base + m * 4);
        }
        cp_commit();
    }
    __syncthreads();

    // roles
    const int j   = t >> 2, seg = t & 3;           // dots
    const int i0  = seg * 2;                        // this lane's 2 slots
    const int a_d8 = t & 7, a_s = (t >> 3) & 7, a_jg = t >> 6;  // accum
    float4 acc0 = {0.f,0.f,0.f,0.f}, acc1 = {0.f,0.f,0.f,0.f};
    float Wp0 = 0.f, Wp1 = 0.f, Tp0 = 0.f, Tp1 = 0.f;

    for (int tt = 0; tt < 8; ++tt) {
        float4* kt4 = (float4*)(sm + ((tt & 1) ? AQ_KT1 : AQ_KT0));
        if (tt < 7) {
            const float* src = base + (tt + 1) * 64 * 64;
            float* kb = sm + (((tt + 1) & 1) ? AQ_KT1 : AQ_KT0);
            #pragma unroll
            for (int k2 = 0; k2 < 4; ++k2) {
                int m = t + k2 * 256;
                cp16(kb + (m >> 4) * 68 + (m & 15) * 4, src + m * 4);
            }
            cp_commit();
            asm volatile("cp.async.wait_group 1;\n");
        } else {
            asm volatile("cp.async.wait_group 0;\n");
        }
        __syncthreads();

        // ---- dots: x read once per (token, seg), s/ss once per token ----
        {
            float s = 0.f, ss = 0.f;
            float dp[8];
            #pragma unroll
            for (int i = 0; i < 8; ++i) dp[i] = 0.f;
            const float4* xrow = kt4 + j * 17 + seg * 4;
            const float4* qg4  = (const float4*)(sm + AQ_QG);
            #pragma unroll
            for (int c = 0; c < 4; ++c) {
                float4 x4 = xrow[c];
                s  += (x4.x + x4.y) + (x4.z + x4.w);
                ss += x4.x * x4.x + x4.y * x4.y + x4.z * x4.z + x4.w * x4.w;
                #pragma unroll
                for (int i = 0; i < 8; ++i) {
                    float4 q4 = qg4[i * 17 + seg * 4 + c];
                    dp[i] += x4.x * q4.x + x4.y * q4.y + x4.z * q4.z + x4.w * q4.w;
                }
            }
            s  += __shfl_xor_sync(~0u, s, 1);  s  += __shfl_xor_sync(~0u, s, 2);
            ss += __shfl_xor_sync(~0u, ss, 1); ss += __shfl_xor_sync(~0u, ss, 2);
            #pragma unroll
            for (int i = 0; i < 8; ++i) {
                dp[i] += __shfl_xor_sync(~0u, dp[i], 1);
                dp[i] += __shfl_xor_sync(~0u, dp[i], 2);
            }
            float m = s * (1.f / 64.f);
            float var = ss * (1.f / 64.f) - m * m;
            float rstd = rsqrtf(var + 1e-5f);
            float mr = m * rstd;
            // this lane's two slots
            float dv0 = rstd * dp[i0]     - mr * sm[AQ_QGS + i0]     + sm[AQ_QB + i0];
            float dv1 = rstd * dp[i0 + 1] - mr * sm[AQ_QGS + i0 + 1] + sm[AQ_QB + i0 + 1];
            float mx = fmaxf(dv0, dv1);
            mx = fmaxf(mx, __shfl_xor_sync(~0u, mx, 1));
            mx = fmaxf(mx, __shfl_xor_sync(~0u, mx, 2));
            float e0 = __expf(dv0 - mx), e1 = __expf(dv1 - mx);
            float sum = e0 + e1;
            sum += __shfl_xor_sync(~0u, sum, 1);
            sum += __shfl_xor_sync(~0u, sum, 2);
            float inv = 1.0f / sum;
            float w0 = e0 * inv + EPSA, w1 = e1 * inv + EPSA;
            float wp0 = w0 * rstd, wp1 = w1 * rstd;
            ((float2*)(sm + AQ_WT2))[j * 4 + seg] = make_float2(wp0, wp1);
            Wp0 += w0; Wp1 += w1;
            Tp0 += wp0 * m; Tp1 += wp1 * m;
        }
        __syncthreads();

        // ---- accumulate A = sum_j w'_ij x_j ----
        #pragma unroll 4
        for (int k = 0; k < 16; ++k) {
            int jj = a_jg * 16 + k;
            float wp = sm[AQ_WT2 + jj * 8 + a_s];
            float4 x0 = kt4[jj * 17 + a_d8];
            float4 x1 = kt4[jj * 17 + a_d8 + 8];
            acc0.x += wp * x0.x; acc0.y += wp * x0.y; acc0.z += wp * x0.z; acc0.w += wp * x0.w;
            acc1.x += wp * x1.x; acc1.y += wp * x1.y; acc1.z += wp * x1.z; acc1.w += wp * x1.w;
        }
        __syncthreads();
    }

    // ---- epilogue: partials to global ----
    ((float4*)(sm + AQ_RED))[t * 2]     = acc0;
    ((float4*)(sm + AQ_RED))[t * 2 + 1] = acc1;
    sm[AQ_WR + j * 8 + i0]     = Wp0;
    sm[AQ_WR + j * 8 + i0 + 1] = Wp1;
    sm[AQ_TR + j * 8 + i0]     = Tp0;
    sm[AQ_TR + j * 8 + i0 + 1] = Tp1;
    __syncthreads();
    for (int e = t; e < 512; e += 256) {
        int i = e >> 6, d = e & 63;
        int d4 = d >> 2, c = d4 >> 3, d8r = d4 & 7, ee = d & 3;
        float A = 0.f;
        #pragma unroll
        for (int jg = 0; jg < 4; ++jg)
            A += sm[AQ_RED + (jg * 64 + i * 8 + d8r) * 8 + c * 4 + ee];
        g_pA[((b * 8 + chunk) * 8 + i) * 64 + d] = A;
    }
    if (t < 8) {
        float w = 0.f, ti = 0.f;
        #pragma unroll 8
        for (int jj = 0; jj < 64; ++jj) { w += sm[AQ_WR + jj * 8 + t]; ti += sm[AQ_TR + jj * 8 + t]; }
        g_pW[(b * 8 + chunk) * 8 + t] = w;
        g_pT[(b * 8 + chunk) * 8 + t] = ti;
    }
}

// =======================================================================
// INIT: 2048 blocks (batch x slot) x 64 threads
// =======================================================================
__global__ __launch_bounds__(64) void init_kernel(
    const float* __restrict__ slots_in, const float* __restrict__ prior_slots,
    const float* __restrict__ eps_noise,
    const float* __restrict__ ni_g, const float* __restrict__ ni_b,
    const float* __restrict__ sr_W1, const float* __restrict__ sr_b1,
    const float* __restrict__ sr_W2, const float* __restrict__ sr_b2,
    const float* __restrict__ pr_W1, const float* __restrict__ pr_b1,
    const float* __restrict__ pr_W2, const float* __restrict__ pr_b2,
    const float* __restrict__ Wq, const float* __restrict__ bq,
    const float* __restrict__ Wk, const float* __restrict__ bk)
{
    __shared__ float P0[64], SL0[64], PH1[128], SLN[64], QT[64], scr[4];
    const int blk = blockIdx.x, b = blk >> 3, i = blk & 7;
    const int t = threadIdx.x;
    const long row = (long)b * 512 + i * 64;

    P0[t]  = prior_slots[row + t];
    SL0[t] = slots_in[row + t];
    if (t == 0) g_kl[b * 8 + i] = 0.f;
    __syncthreads();

    // prior hidden
    {
        const float4* p4 = (const float4*)P0;
        const float4* w0 = (const float4*)(pr_W1 + t * 64);
        const float4* w1 = (const float4*)(pr_W1 + (64 + t) * 64);
        float a0 = 0.f, a1 = 0.f;
        #pragma unroll 4
        for (int k = 0; k < 16; ++k) {
            float4 p = p4[k], wa = w0[k], wb = w1[k];
            a0 += wa.x * p.x + wa.y * p.y + wa.z * p.z + wa.w * p.w;
            a1 += wb.x * p.x + wb.y * p.y + wb.z * p.z + wb.w * p.w;
        }
        PH1[t]      = fmaxf(a0 + pr_b1[t], 0.f);
        PH1[64 + t] = fmaxf(a1 + pr_b1[64 + t], 0.f);
    }
    __syncthreads();
    // prior out -> g_prior
    {
        const float4* p4 = (const float4*)PH1;
        const float4* w0 = (const float4*)(pr_W2 + t * 128);
        const float4* w1 = (const float4*)(pr_W2 + (64 + t) * 128);
        float a0 = 0.f, a1 = 0.f;
        #pragma unroll 4
        for (int k = 0; k < 32; ++k) {
            float4 p = p4[k], wa = w0[k], wb = w1[k];
            a0 += wa.x * p.x + wa.y * p.y + wa.z * p.z + wa.w * p.w;
            a1 += wb.x * p.x + wb.y * p.y + wb.z * p.z + wb.w * p.w;
        }
        g_prior[(long)b * 1024 + i * 128 + t]      = a0 + pr_b2[t];
        g_prior[(long)b * 1024 + i * 128 + 64 + t] = a1 + pr_b2[64 + t];
    }
    __syncthreads();
    // posterior hidden on initial slots (reuse PH1)
    {
        const float4* s4 = (const float4*)SL0;
        const float4* w0 = (const float4*)(sr_W1 + t * 64);
        const float4* w1 = (const float4*)(sr_W1 + (64 + t) * 64);
        float a0 = 0.f, a1 = 0.f;
        #pragma unroll 4
        for (int k = 0; k < 16; ++k) {
            float4 p = s4[k], wa = w0[k], wb = w1[k];
            a0 += wa.x * p.x + wa.y * p.y + wa.z * p.z + wa.w * p.w;
            a1 += wb.x * p.x + wb.y * p.y + wb.z * p.z + wb.w * p.w;
        }
        PH1[t]      = fmaxf(a0 + sr_b1[t], 0.f);
        PH1[64 + t] = fmaxf(a1 + sr_b1[64 + t], 0.f);
    }
    __syncthreads();
    // posterior out (rows t = mu_t, 64+t = lv_t) + reparameterize
    {
        const float4* p4 = (const float4*)PH1;
        const float4* w0 = (const float4*)(sr_W2 + t * 128);
        const float4* w1 = (const float4*)(sr_W2 + (64 + t) * 128);
        float a0 = 0.f, a1 = 0.f;
        #pragma unroll 4
        for (int k = 0; k < 32; ++k) {
            float4 p = p4[k], wa = w0[k], wb = w1[k];
            a0 += wa.x * p.x + wa.y * p.y + wa.z * p.z + wa.w * p.w;
            a1 += wb.x * p.x + wb.y * p.y + wb.z * p.z + wb.w * p.w;
        }
        float mu = a0 + sr_b2[t], lv = a1 + sr_b2[64 + t];
        float sl = eps_noise[row + t] * expf(0.5f * lv) + mu;
        SLN[t] = sl;
        g_slots[row + t] = sl;
    }
    __syncthreads();
    // q projection for iter 0
    {
        const float4* s4 = (const float4*)SLN;
        const float4* w4 = (const float4*)(Wq + t * 64);
        float a = 0.f;
        #pragma unroll 4
        for (int k = 0; k < 16; ++k) {
            float4 p = s4[k], w = w4[k];
            a += w.x * p.x + w.y * p.y + w.z * p.z + w.w * p.w;
        }
        QT[t] = a + bq[t];
    }
    __syncthreads();
    {
        float qp = 0.f;
        #pragma unroll 8
        for (int o = 0; o < 64; ++o) qp += QT[o] * __ldg(Wk + o * 64 + t);
        qp *= SCALEF;
        float qgv = qp * ni_g[t];
        g_qg[row + t] = qgv;
        float c1 = qgv;
        float c2 = qp * ni_b[t] + SCALEF * QT[t] * bk[t];
        red64x2(c1, c2, scr, t);
        if (t == 0) { g_qgs[b * 8 + i] = c1; g_qb[b * 8 + i] = c2; }
    }
}

// =======================================================================
// UPDATE: 2048 blocks (batch x slot) x 64 threads
// =======================================================================
__global__ __launch_bounds__(64) void update_kernel(
    const float* __restrict__ Wv, const float* __restrict__ bv,
    const float* __restrict__ gru_Wih, const float* __restrict__ gru_Whh,
    const float* __restrict__ gru_bih, const float* __restrict__ gru_bhh,
    const float* __restrict__ npf_g, const float* __restrict__ npf_b,
    const float* __restrict__ mlp_W1, const float* __restrict__ mlp_b1,
    const float* __restrict__ mlp_W2, const float* __restrict__ mlp_b2,
    const float* __restrict__ sr_W1, const float* __restrict__ sr_b1,
    const float* __restrict__ sr_W2, const float* __restrict__ sr_b2,
    const float* __restrict__ ni_g, const float* __restrict__ ni_b,
    const float* __restrict__ Wq, const float* __restrict__ bq,
    const float* __restrict__ Wk, const float* __restrict__ bk,
    int final_iter, float* __restrict__ out)
{
    __shared__ float NUM[64], U[64], SL[64], LNX[64], HID[128], PH[128], SLN[64], QT[64], scr[4];
    const int blk = blockIdx.x, b = blk >> 3, i = blk & 7;
    const int t = threadIdx.x;
    const long row = (long)b * 512 + i * 64;

    SL[t] = g_slots[row + t];
    float den = 0.f, ti = 0.f, A = 0.f;
    #pragma unroll
    for (int c = 0; c < 8; ++c) {
        den += g_pW[(b * 8 + c) * 8 + i];
        ti  += g_pT[(b * 8 + c) * 8 + i];
        A   += g_pA[((b * 8 + c) * 8 + i) * 64 + t];
    }
    NUM[t] = ni_g[t] * (A - ti) * (1.0f / den) + ni_b[t];
    __syncthreads();
    // u = Wv @ NUM + bv
    {
        const float4* n4 = (const float4*)NUM;
        const float4* w4 = (const float4*)(Wv + t * 64);
        float a = 0.f;
        #pragma unroll 4
        for (int k = 0; k < 16; ++k) {
            float4 w = w4[k], n = n4[k];
            a += w.x * n.x + w.y * n.y + w.z * n.z + w.w * n.w;
        }
        U[t] = a + bv[t];
    }
    __syncthreads();
    // GRU (thread t owns dim t: all 6 gate dots)
    float hn;
    {
        const float4* u4 = (const float4*)U;
        const float4* s4 = (const float4*)SL;
        const float4* wir = (const float4*)(gru_Wih + t * 64);
        const float4* wiz = (const float4*)(gru_Wih + (64 + t) * 64);
        const float4* win = (const float4*)(gru_Wih + (128 + t) * 64);
        const float4* whr = (const float4*)(gru_Whh + t * 64);
        const float4* whz = (const float4*)(gru_Whh + (64 + t) * 64);
        const float4* whn = (const float4*)(gru_Whh + (128 + t) * 64);
        float gir = 0.f, giz = 0.f, gin = 0.f, ghr = 0.f, ghz = 0.f, ghn = 0.f;
        #pragma unroll 2
        for (int k = 0; k < 16; ++k) {
            float4 uv = u4[k], sv = s4[k];
            float4 w;
            w = wir[k]; gir += w.x * uv.x + w.y * uv.y + w.z * uv.z + w.w * uv.w;
            w = wiz[k]; giz += w.x * uv.x + w.y * uv.y + w.z * uv.z + w.w * uv.w;
            w = win[k]; gin += w.x * uv.x + w.y * uv.y + w.z * uv.z + w.w * uv.w;
            w = whr[k]; ghr += w.x * sv.x + w.y * sv.y + w.z * sv.z + w.w * sv.w;
            w = whz[k]; ghz += w.x * sv.x + w.y * sv.y + w.z * sv.z + w.w * sv.w;
            w = whn[k]; ghn += w.x * sv.x + w.y * sv.y + w.z * sv.z + w.w * sv.w;
        }
        float r = sigmoidf_(gir + gru_bih[t] + ghr + gru_bhh[t]);
        float z = sigmoidf_(giz + gru_bih[64 + t] + ghz + gru_bhh[64 + t]);
        float n = tanhf(gin + gru_bih[128 + t] + r * (ghn + gru_bhh[128 + t]));
        hn = (1.f - z) * n + z * SL[t];
    }
    // LN(hn)
    {
        float s = hn, ss = hn * hn;
        red64x2(s, ss, scr, t);
        float m = s * (1.f / 64.f);
        float var = ss * (1.f / 64.f) - m * m;
        float rstd = rsqrtf(var + 1e-5f);
        LNX[t] = (hn - m) * rstd * npf_g[t] + npf_b[t];
    }
    __syncthreads();
    // mlp hidden
    {
        const float4* l4 = (const float4*)LNX;
        const float4* w0 = (const float4*)(mlp_W1 + t * 64);
        const float4* w1 = (const float4*)(mlp_W1 + (64 + t) * 64);
        float a0 = 0.f, a1 = 0.f;
        #pragma unroll 4
        for (int k = 0; k < 16; ++k) {
            float4 l = l4[k], wa = w0[k], wb = w1[k];
            a0 += wa.x * l.x + wa.y * l.y + wa.z * l.z + wa.w * l.w;
            a1 += wb.x * l.x + wb.y * l.y + wb.z * l.z + wb.w * l.w;
        }
        HID[t]      = fmaxf(a0 + mlp_b1[t], 0.f);
        HID[64 + t] = fmaxf(a1 + mlp_b1[64 + t], 0.f);
    }
    __syncthreads();
    // mlp out + residual
    float sln;
    {
        const float4* h4 = (const float4*)HID;
        const float4* w4 = (const float4*)(mlp_W2 + t * 128);
        float a = 0.f;
        #pragma unroll 4
        for (int k = 0; k < 32; ++k) {
            float4 h = h4[k], w = w4[k];
            a += w.x * h.x + w.y * h.y + w.z * h.z + w.w * h.w;
        }
        sln = hn + a + mlp_b2[t];
        SLN[t] = sln;
        g_slots[row + t] = sln;
    }
    __syncthreads();
    // posterior hidden
    {
        const float4* s4 = (const float4*)SLN;
        const float4* w0 = (const float4*)(sr_W1 + t * 64);
        const float4* w1 = (const float4*)(sr_W1 + (64 + t) * 64);
        float a0 = 0.f, a1 = 0.f;
        #pragma unroll 4
        for (int k = 0; k < 16; ++k) {
            float4 p = s4[k], wa = w0[k], wb = w1[k];
            a0 += wa.x * p.x + wa.y * p.y + wa.z * p.z + wa.w * p.w;
            a1 += wb.x * p.x + wb.y * p.y + wb.z * p.z + wb.w * p.w;
        }
        PH[t]      = fmaxf(a0 + sr_b1[t], 0.f);
        PH[64 + t] = fmaxf(a1 + sr_b1[64 + t], 0.f);
    }
    __syncthreads();
    // posterior out (thread t computes mu_t and lv_t) + KL
    {
        const float4* p4 = (const float4*)PH;
        const float4* w0 = (const float4*)(sr_W2 + t * 128);
        const float4* w1 = (const float4*)(sr_W2 + (64 + t) * 128);
        float a0 = 0.f, a1 = 0.f;
        #pragma unroll 4
        for (int k = 0; k < 32; ++k) {
            float4 p = p4[k], wa = w0[k], wb = w1[k];
            a0 += wa.x * p.x + wa.y * p.y + wa.z * p.z + wa.w * p.w;
            a1 += wb.x * p.x + wb.y * p.y + wb.z * p.z + wb.w * p.w;
        }
        float po_m = a0 + sr_b2[t], po_lv = a1 + sr_b2[64 + t];
        float m_pr  = g_prior[(long)b * 1024 + i * 128 + t];
        float lv_pr = g_prior[(long)b * 1024 + i * 128 + 64 + t];
        float dm = po_m - m_pr;
        float term = lv_pr - po_lv + (expf(po_lv) + dm * dm) * expf(-lv_pr) - 1.0f;
        float dummy = 0.f;
        red64x2(term, dummy, scr, t);
        if (t == 0) {
            float v = g_kl[b * 8 + i] + 0.5f * term;
            g_kl[b * 8 + i] = v;
            if (final_iter) out[131072 + b * 8 + i] = v;
        }
    }
    if (final_iter) {
        out[row + t] = sln;
    } else {
        // q projection for next iteration
        {
            const float4* s4 = (const float4*)SLN;
            const float4* w4 = (const float4*)(Wq + t * 64);
            float a = 0.f;
            #pragma unroll 4
            for (int k = 0; k < 16; ++k) {
                float4 p = s4[k], w = w4[k];
                a += w.x * p.x + w.y * p.y + w.z * p.z + w.w * p.w;
            }
            QT[t] = a + bq[t];
        }
        __syncthreads();
        float qp = 0.f;
        #pragma unroll 8
        for (int o = 0; o < 64; ++o) qp += QT[o] * __ldg(Wk + o * 64 + t);
        qp *= SCALEF;
        float qgv = qp * ni_g[t];
        g_qg[row + t] = qgv;
        float c1 = qgv;
        float c2 = qp * ni_b[t] + SCALEF * QT[t] * bk[t];
        red64x2(c1, c2, scr, t);
        if (t == 0) { g_qgs[b * 8 + i] = c1; g_qb[b * 8 + i] = c2; }
    }
}

// =======================================================================
extern "C" void kernel_launch(void* const* d_in, const int* in_sizes, int n_in,
                              void* d_out, int out_size)
{
    const float* inputs      = (const float*)d_in[0];
    const float* slots       = (const float*)d_in[1];
    const float* prior_slots = (const float*)d_in[2];
    const float* eps_noise   = (const float*)d_in[3];
    const float* ni_g  = (const float*)d_in[4];
    const float* ni_b  = (const float*)d_in[5];
    const float* npf_g = (const float*)d_in[6];
    const float* npf_b = (const float*)d_in[7];
    const float* Wq = (const float*)d_in[8];
    const float* bq = (const float*)d_in[9];
    const float* Wk = (const float*)d_in[10];
    const float* bk = (const float*)d_in[11];
    const float* Wv = (const float*)d_in[12];
    const float* bv = (const float*)d_in[13];
    const float* sr_W1 = (const float*)d_in[14];
    const float* sr_b1 = (const float*)d_in[15];
    const float* sr_W2 = (const float*)d_in[16];
    const float* sr_b2 = (const float*)d_in[17];
    const float* pr_W1 = (const float*)d_in[18];
    const float* pr_b1 = (const float*)d_in[19];
    const float* pr_W2 = (const float*)d_in[20];
    const float* pr_b2 = (const float*)d_in[21];
    const float* gru_Wih = (const float*)d_in[22];
    const float* gru_Whh = (const float*)d_in[23];
    const float* gru_bih = (const float*)d_in[24];
    const float* gru_bhh = (const float*)d_in[25];
    const float* mlp_W1 = (const float*)d_in[26];
    const float* mlp_b1 = (const float*)d_in[27];
    const float* mlp_W2 = (const float*)d_in[28];
    const float* mlp_b2 = (const float*)d_in[29];

    cudaFuncSetAttribute(attn_kernel, cudaFuncAttributeMaxDynamicSharedMemorySize, AQ_BYTES);

    init_kernel<<<NBATCH * 8, 64>>>(slots, prior_slots, eps_noise,
                                    ni_g, ni_b,
                                    sr_W1, sr_b1, sr_W2, sr_b2,
                                    pr_W1, pr_b1, pr_W2, pr_b2,
                                    Wq, bq, Wk, bk);
    for (int it = 0; it < 3; ++it) {
        attn_kernel<<<NBATCH * 8, 256, AQ_BYTES>>>(inputs);
        update_kernel<<<NBATCH * 8, 64>>>(Wv, bv,
                                          gru_Wih, gru_Whh, gru_bih, gru_bhh,
                                          npf_g, npf_b,
                                          mlp_W1, mlp_b1, mlp_W2, mlp_b2,
                                          sr_W1, sr_b1, sr_W2, sr_b2,
                                          ni_g, ni_b, Wq, bq, Wk, bk,
                                          it == 2 ? 1 : 0, (float*)d_out);
    }
}

// round 14
// speedup vs baseline: 6.0988x; 1.4759x over previous
#include <cuda_runtime.h>

#define NBATCH 256
#define NTOK   4096
#define NCH    16
#define SCALEF 0.125f
#define EPSA   1e-8f

// ---------------- global scratch ----------------
__device__ float g_slots[NBATCH * 512];
__device__ float g_prior[NBATCH * 1024];
__device__ float g_kl[NBATCH * 8];
__device__ float g_qg[NBATCH * 512];
__device__ float g_qgs[NBATCH * 8];
__device__ float g_qb[NBATCH * 8];
__device__ float g_pA[NBATCH * NCH * 8 * 64];
__device__ float g_pW[NBATCH * NCH * 8];
__device__ float g_pT[NBATCH * NCH * 8];

__device__ __forceinline__ void cp16(float* smem_dst, const float* gsrc) {
    unsigned dst = (unsigned)__cvta_generic_to_shared(smem_dst);
    asm volatile("cp.async.cg.shared.global [%0], [%1], 16;\n" :: "r"(dst), "l"(gsrc));
}
__device__ __forceinline__ void cp_commit() { asm volatile("cp.async.commit_group;\n"); }
__device__ __forceinline__ float sigmoidf_(float x) { return 1.0f / (1.0f + expf(-x)); }
__device__ __forceinline__ float dot4(float4 a, float4 b) {
    return a.x * b.x + a.y * b.y + a.z * b.z + a.w * b.w;
}

// =======================================================================
// ATTENTION: 4096 blocks (batch x 16 chunks of 256 tokens) x 256 threads
// =======================================================================
#define AQ_QG  0           // [8][68]
#define AQ_QGS 544
#define AQ_QB  552
#define AQ_WT2 560         // [64 tokens][8 slots] w'
#define AQ_WR  1072        // [64][8]
#define AQ_TR  1584        // [64][8]
#define AQ_KT0 2096        // [64][68]
#define AQ_KT1 6448
#define AQ_RED AQ_KT0      // epilogue alias (last tile uses KT1)
#define AQ_TOT 10800
#define AQ_BYTES (AQ_TOT * 4)

__global__ __launch_bounds__(256, 4) void attn_kernel(const float* __restrict__ inputs)
{
    extern __shared__ float sm[];
    const int blk = blockIdx.x;
    const int b = blk >> 4, chunk = blk & 15;
    const int t = threadIdx.x;

    for (int e = t; e < 512; e += 256)
        sm[AQ_QG + (e >> 6) * 68 + (e & 63)] = g_qg[b * 512 + e];
    if (t < 8) { sm[AQ_QGS + t] = g_qgs[b * 8 + t]; sm[AQ_QB + t] = g_qb[b * 8 + t]; }

    const float* base = inputs + ((long)b * NTOK + chunk * 256) * 64;
    {
        float* kb = sm + AQ_KT0;
        #pragma unroll
        for (int k2 = 0; k2 < 4; ++k2) {
            int m = t + k2 * 256;
            cp16(kb + (m >> 4) * 68 + (m & 15) * 4, base + m * 4);
        }
        cp_commit();
    }
    __syncthreads();

    // dots roles
    const int j = t >> 2, seg = t & 3;
    const int i0 = seg * 2;
    // accum roles
    const int a_d8 = t & 7, a_p = (t >> 3) & 3, a_jg = t >> 5;
    float4 a00 = {0,0,0,0}, a01 = {0,0,0,0}, a10 = {0,0,0,0}, a11 = {0,0,0,0};
    float Wp0 = 0.f, Wp1 = 0.f, Tp0 = 0.f, Tp1 = 0.f;

    for (int tt = 0; tt < 4; ++tt) {
        float4* kt4 = (float4*)(sm + ((tt & 1) ? AQ_KT1 : AQ_KT0));
        if (tt < 3) {
            const float* src = base + (tt + 1) * 64 * 64;
            float* kb = sm + (((tt + 1) & 1) ? AQ_KT1 : AQ_KT0);
            #pragma unroll
            for (int k2 = 0; k2 < 4; ++k2) {
                int m = t + k2 * 256;
                cp16(kb + (m >> 4) * 68 + (m & 15) * 4, src + m * 4);
            }
            cp_commit();
            asm volatile("cp.async.wait_group 1;\n");
        } else {
            asm volatile("cp.async.wait_group 0;\n");
        }
        __syncthreads();

        // ---- dots (LN folded) ----
        {
            float s = 0.f, ss = 0.f;
            float dp[8];
            #pragma unroll
            for (int i = 0; i < 8; ++i) dp[i] = 0.f;
            const float4* xrow = kt4 + j * 17 + seg * 4;
            const float4* qg4  = (const float4*)(sm + AQ_QG);
            #pragma unroll
            for (int c = 0; c < 4; ++c) {
                float4 x4 = xrow[c];
                s  += (x4.x + x4.y) + (x4.z + x4.w);
                ss += x4.x * x4.x + x4.y * x4.y + x4.z * x4.z + x4.w * x4.w;
                #pragma unroll
                for (int i = 0; i < 8; ++i)
                    dp[i] += dot4(x4, qg4[i * 17 + seg * 4 + c]);
            }
            s  += __shfl_xor_sync(~0u, s, 1);  s  += __shfl_xor_sync(~0u, s, 2);
            ss += __shfl_xor_sync(~0u, ss, 1); ss += __shfl_xor_sync(~0u, ss, 2);
            #pragma unroll
            for (int i = 0; i < 8; ++i) {
                dp[i] += __shfl_xor_sync(~0u, dp[i], 1);
                dp[i] += __shfl_xor_sync(~0u, dp[i], 2);
            }
            float m = s * (1.f / 64.f);
            float var = ss * (1.f / 64.f) - m * m;
            float rstd = rsqrtf(var + 1e-5f);
            float mr = m * rstd;
            float dv0 = rstd * dp[i0]     - mr * sm[AQ_QGS + i0]     + sm[AQ_QB + i0];
            float dv1 = rstd * dp[i0 + 1] - mr * sm[AQ_QGS + i0 + 1] + sm[AQ_QB + i0 + 1];
            float mx = fmaxf(dv0, dv1);
            mx = fmaxf(mx, __shfl_xor_sync(~0u, mx, 1));
            mx = fmaxf(mx, __shfl_xor_sync(~0u, mx, 2));
            float e0 = __expf(dv0 - mx), e1 = __expf(dv1 - mx);
            float sum = e0 + e1;
            sum += __shfl_xor_sync(~0u, sum, 1);
            sum += __shfl_xor_sync(~0u, sum, 2);
            float inv = 1.0f / sum;
            float w0 = e0 * inv + EPSA, w1 = e1 * inv + EPSA;
            float wp0 = w0 * rstd, wp1 = w1 * rstd;
            ((float2*)(sm + AQ_WT2))[j * 4 + seg] = make_float2(wp0, wp1);
            Wp0 += w0; Wp1 += w1;
            Tp0 += wp0 * m; Tp1 += wp1 * m;
        }
        __syncthreads();

        // ---- accumulate: 2 slots per thread, x read once per pair ----
        #pragma unroll
        for (int k = 0; k < 8; ++k) {
            int jj = a_jg * 8 + k;
            float2 wp = ((float2*)(sm + AQ_WT2))[jj * 4 + a_p];
            float4 x0 = kt4[jj * 17 + a_d8];
            float4 x1 = kt4[jj * 17 + a_d8 + 8];
            a00.x += wp.x * x0.x; a00.y += wp.x * x0.y; a00.z += wp.x * x0.z; a00.w += wp.x * x0.w;
            a01.x += wp.x * x1.x; a01.y += wp.x * x1.y; a01.z += wp.x * x1.z; a01.w += wp.x * x1.w;
            a10.x += wp.y * x0.x; a10.y += wp.y * x0.y; a10.z += wp.y * x0.z; a10.w += wp.y * x0.w;
            a11.x += wp.y * x1.x; a11.y += wp.y * x1.y; a11.z += wp.y * x1.z; a11.w += wp.y * x1.w;
        }
        __syncthreads();
    }

    // ---- epilogue ----
    {
        float4* red = (float4*)(sm + AQ_RED);
        red[t * 4 + 0] = a00; red[t * 4 + 1] = a01;
        red[t * 4 + 2] = a10; red[t * 4 + 3] = a11;
        sm[AQ_WR + j * 8 + i0]     = Wp0;
        sm[AQ_WR + j * 8 + i0 + 1] = Wp1;
        sm[AQ_TR + j * 8 + i0]     = Tp0;
        sm[AQ_TR + j * 8 + i0 + 1] = Tp1;
    }
    __syncthreads();
    for (int e = t; e < 512; e += 256) {
        int i = e >> 6, d = e & 63;
        int pair = i >> 1, comp = i & 1, half = d >> 5, d8 = (d & 31) >> 2, elem = d & 3;
        int c = comp * 2 + half;
        float A = 0.f;
        #pragma unroll
        for (int jg = 0; jg < 8; ++jg) {
            int tp = jg * 32 + pair * 8 + d8;
            A += sm[AQ_RED + tp * 16 + c * 4 + elem];
        }
        g_pA[((b * NCH + chunk) * 8 + i) * 64 + d] = A;
    }
    if (t < 8) {
        float w = 0.f, ti = 0.f;
        #pragma unroll 8
        for (int jj = 0; jj < 64; ++jj) { w += sm[AQ_WR + jj * 8 + t]; ti += sm[AQ_TR + jj * 8 + t]; }
        g_pW[(b * NCH + chunk) * 8 + t] = w;
        g_pT[(b * NCH + chunk) * 8 + t] = ti;
    }
}

// =======================================================================
// INIT: 256 blocks (batch) x 128 threads, weights streamed once per block
// =======================================================================
__global__ __launch_bounds__(128) void init_kernel(
    const float* __restrict__ slots_in, const float* __restrict__ prior_slots,
    const float* __restrict__ eps_noise,
    const float* __restrict__ ni_g, const float* __restrict__ ni_b,
    const float* __restrict__ sr_W1, const float* __restrict__ sr_b1,
    const float* __restrict__ sr_W2, const float* __restrict__ sr_b2,
    const float* __restrict__ pr_W1, const float* __restrict__ pr_b1,
    const float* __restrict__ pr_W2, const float* __restrict__ pr_b2,
    const float* __restrict__ Wq, const float* __restrict__ bq,
    const float* __restrict__ Wk, const float* __restrict__ bk)
{
    __shared__ float P0[512], S0[512], B1[1024], B2[1024], SLN[512], QT[512];
    __shared__ float RD1[128], RD2[128];
    const int b = blockIdx.x, t = threadIdx.x;
    const int tt = t & 63, r0 = (t >> 6) * 4;

    for (int e = t; e < 512; e += 128) {
        P0[e] = prior_slots[(long)b * 512 + e];
        S0[e] = slots_in[(long)b * 512 + e];
    }
    if (t < 8) g_kl[b * 8 + t] = 0.f;
    __syncthreads();
    // prior hidden (od = t, 8 rows)
    {
        float acc[8] = {0,0,0,0,0,0,0,0};
        const float4* w4 = (const float4*)(pr_W1 + t * 64);
        const float4* p4 = (const float4*)P0;
        #pragma unroll 4
        for (int k = 0; k < 16; ++k) {
            float4 w = __ldg(w4 + k);
            #pragma unroll
            for (int i = 0; i < 8; ++i) acc[i] += dot4(w, p4[i * 16 + k]);
        }
        float b1 = __ldg(pr_b1 + t);
        #pragma unroll
        for (int i = 0; i < 8; ++i) B1[i * 128 + t] = fmaxf(acc[i] + b1, 0.f);
    }
    __syncthreads();
    // prior out -> g_prior
    {
        float acc[8] = {0,0,0,0,0,0,0,0};
        const float4* w4 = (const float4*)(pr_W2 + t * 128);
        const float4* h4 = (const float4*)B1;
        #pragma unroll 4
        for (int k = 0; k < 32; ++k) {
            float4 w = __ldg(w4 + k);
            #pragma unroll
            for (int i = 0; i < 8; ++i) acc[i] += dot4(w, h4[i * 32 + k]);
        }
        float b2 = __ldg(pr_b2 + t);
        #pragma unroll
        for (int i = 0; i < 8; ++i) g_prior[(long)b * 1024 + i * 128 + t] = acc[i] + b2;
    }
    __syncthreads();
    // posterior hidden on initial slots
    {
        float acc[8] = {0,0,0,0,0,0,0,0};
        const float4* w4 = (const float4*)(sr_W1 + t * 64);
        const float4* s4 = (const float4*)S0;
        #pragma unroll 4
        for (int k = 0; k < 16; ++k) {
            float4 w = __ldg(w4 + k);
            #pragma unroll
            for (int i = 0; i < 8; ++i) acc[i] += dot4(w, s4[i * 16 + k]);
        }
        float b1 = __ldg(sr_b1 + t);
        #pragma unroll
        for (int i = 0; i < 8; ++i) B1[i * 128 + t] = fmaxf(acc[i] + b1, 0.f);
    }
    __syncthreads();
    // posterior out -> B2
    {
        float acc[8] = {0,0,0,0,0,0,0,0};
        const float4* w4 = (const float4*)(sr_W2 + t * 128);
        const float4* h4 = (const float4*)B1;
        #pragma unroll 4
        for (int k = 0; k < 32; ++k) {
            float4 w = __ldg(w4 + k);
            #pragma unroll
            for (int i = 0; i < 8; ++i) acc[i] += dot4(w, h4[i * 32 + k]);
        }
        float b2 = __ldg(sr_b2 + t);
        #pragma unroll
        for (int i = 0; i < 8; ++i) B2[i * 128 + t] = acc[i] + b2;
    }
    __syncthreads();
    // reparameterize
    for (int e = t; e < 512; e += 128) {
        int i = e >> 6, d = e & 63;
        float mu = B2[i * 128 + d], lv = B2[i * 128 + 64 + d];
        float v = eps_noise[(long)b * 512 + e] * expf(0.5f * lv) + mu;
        SLN[e] = v;
        g_slots[(long)b * 512 + e] = v;
    }
    __syncthreads();
    // q projection
    {
        float acc[4] = {0,0,0,0};
        const float4* w4 = (const float4*)(Wq + tt * 64);
        const float4* s4 = (const float4*)SLN;
        #pragma unroll 4
        for (int k = 0; k < 16; ++k) {
            float4 w = __ldg(w4 + k);
            #pragma unroll
            for (int r = 0; r < 4; ++r) acc[r] += dot4(w, s4[(r0 + r) * 16 + k]);
        }
        float bb = __ldg(bq + tt);
        #pragma unroll
        for (int r = 0; r < 4; ++r) QT[(r0 + r) * 64 + tt] = acc[r] + bb;
    }
    __syncthreads();
    {
        float qp[4] = {0,0,0,0};
        for (int o = 0; o < 64; ++o) {
            float w = __ldg(Wk + o * 64 + tt);
            #pragma unroll
            for (int r = 0; r < 4; ++r) qp[r] += QT[(r0 + r) * 64 + o] * w;
        }
        float gg = ni_g[tt], nb = ni_b[tt], bkt = bk[tt];
        #pragma unroll
        for (int r = 0; r < 4; ++r) {
            int i = r0 + r;
            float q = qp[r] * SCALEF;
            float qgv = q * gg;
            g_qg[(long)b * 512 + i * 64 + tt] = qgv;
            B1[i * 64 + tt] = qgv;
            B1[512 + i * 64 + tt] = q * nb + SCALEF * QT[i * 64 + tt] * bkt;
        }
    }
    __syncthreads();
    {
        int ir = t >> 4, d0 = t & 15;
        float s1 = 0.f, s2 = 0.f;
        #pragma unroll
        for (int k = 0; k < 4; ++k) {
            s1 += B1[ir * 64 + d0 + 16 * k];
            s2 += B1[512 + ir * 64 + d0 + 16 * k];
        }
        RD1[t] = s1; RD2[t] = s2;
    }
    __syncthreads();
    if (t < 8) {
        float s1 = 0.f, s2 = 0.f;
        #pragma unroll
        for (int q = 0; q < 16; ++q) { s1 += RD1[t * 16 + q]; s2 += RD2[t * 16 + q]; }
        g_qgs[b * 8 + t] = s1;
        g_qb[b * 8 + t]  = s2;
    }
}

// =======================================================================
// UPDATE: 256 blocks (batch) x 128 threads
// =======================================================================
__global__ __launch_bounds__(128) void update_kernel(
    const float* __restrict__ Wv, const float* __restrict__ bv,
    const float* __restrict__ gru_Wih, const float* __restrict__ gru_Whh,
    const float* __restrict__ gru_bih, const float* __restrict__ gru_bhh,
    const float* __restrict__ npf_g, const float* __restrict__ npf_b,
    const float* __restrict__ mlp_W1, const float* __restrict__ mlp_b1,
    const float* __restrict__ mlp_W2, const float* __restrict__ mlp_b2,
    const float* __restrict__ sr_W1, const float* __restrict__ sr_b1,
    const float* __restrict__ sr_W2, const float* __restrict__ sr_b2,
    const float* __restrict__ ni_g, const float* __restrict__ ni_b,
    const float* __restrict__ Wq, const float* __restrict__ bq,
    const float* __restrict__ Wk, const float* __restrict__ bk,
    int final_iter, float* __restrict__ out)
{
    __shared__ float SL[512], NUM[512], U[512], HN[512], LNX[512], SLN[512], QT[512];
    __shared__ float B1[1024], B2[1024];
    __shared__ float RD1[128], RD2[128], MM[8], RS[8], DINV[8], TI[8];
    const int b = blockIdx.x, t = threadIdx.x;
    const int tt = t & 63, r0 = (t >> 6) * 4;

    for (int e = t; e < 512; e += 128) SL[e] = g_slots[(long)b * 512 + e];
    if (t < 8) {
        float den = 0.f, ti = 0.f;
        #pragma unroll 4
        for (int c = 0; c < NCH; ++c) {
            den += g_pW[(b * NCH + c) * 8 + t];
            ti  += g_pT[(b * NCH + c) * 8 + t];
        }
        DINV[t] = 1.0f / den; TI[t] = ti;
    }
    __syncthreads();
    // NUM
    {
        float gg = ni_g[tt], bb = ni_b[tt];
        #pragma unroll
        for (int r = 0; r < 4; ++r) {
            int i = r0 + r;
            float A = 0.f;
            #pragma unroll 4
            for (int c = 0; c < NCH; ++c) A += g_pA[((b * NCH + c) * 8 + i) * 64 + tt];
            NUM[i * 64 + tt] = gg * (A - TI[i]) * DINV[i] + bb;
        }
    }
    __syncthreads();
    // U = Wv @ NUM + bv
    {
        float acc[4] = {0,0,0,0};
        const float4* w4 = (const float4*)(Wv + tt * 64);
        const float4* n4 = (const float4*)NUM;
        #pragma unroll 4
        for (int k = 0; k < 16; ++k) {
            float4 w = __ldg(w4 + k);
            #pragma unroll
            for (int r = 0; r < 4; ++r) acc[r] += dot4(w, n4[(r0 + r) * 16 + k]);
        }
        float bb = __ldg(bv + tt);
        #pragma unroll
        for (int r = 0; r < 4; ++r) U[(r0 + r) * 64 + tt] = acc[r] + bb;
    }
    __syncthreads();
    // GRU
    {
        const float4* u4 = (const float4*)U;
        const float4* s4 = (const float4*)SL;
        float rr[4], zz[4], nn[4];
        {   // r gate
            float ai[4] = {0,0,0,0}, ah[4] = {0,0,0,0};
            const float4* wi = (const float4*)(gru_Wih + tt * 64);
            const float4* wh = (const float4*)(gru_Whh + tt * 64);
            #pragma unroll 4
            for (int k = 0; k < 16; ++k) {
                float4 a = __ldg(wi + k), h = __ldg(wh + k);
                #pragma unroll
                for (int r = 0; r < 4; ++r) {
                    ai[r] += dot4(a, u4[(r0 + r) * 16 + k]);
                    ah[r] += dot4(h, s4[(r0 + r) * 16 + k]);
                }
            }
            float bi = __ldg(gru_bih + tt), bh = __ldg(gru_bhh + tt);
            #pragma unroll
            for (int r = 0; r < 4; ++r) rr[r] = sigmoidf_(ai[r] + bi + ah[r] + bh);
        }
        {   // z gate
            float ai[4] = {0,0,0,0}, ah[4] = {0,0,0,0};
            const float4* wi = (const float4*)(gru_Wih + (64 + tt) * 64);
            const float4* wh = (const float4*)(gru_Whh + (64 + tt) * 64);
            #pragma unroll 4
            for (int k = 0; k < 16; ++k) {
                float4 a = __ldg(wi + k), h = __ldg(wh + k);
                #pragma unroll
                for (int r = 0; r < 4; ++r) {
                    ai[r] += dot4(a, u4[(r0 + r) * 16 + k]);
                    ah[r] += dot4(h, s4[(r0 + r) * 16 + k]);
                }
            }
            float bi = __ldg(gru_bih + 64 + tt), bh = __ldg(gru_bhh + 64 + tt);
            #pragma unroll
            for (int r = 0; r < 4; ++r) zz[r] = sigmoidf_(ai[r] + bi + ah[r] + bh);
        }
        {   // n gate
            float ai[4] = {0,0,0,0}, ah[4] = {0,0,0,0};
            const float4* wi = (const float4*)(gru_Wih + (128 + tt) * 64);
            const float4* wh = (const float4*)(gru_Whh + (128 + tt) * 64);
            #pragma unroll 4
            for (int k = 0; k < 16; ++k) {
                float4 a = __ldg(wi + k), h = __ldg(wh + k);
                #pragma unroll
                for (int r = 0; r < 4; ++r) {
                    ai[r] += dot4(a, u4[(r0 + r) * 16 + k]);
                    ah[r] += dot4(h, s4[(r0 + r) * 16 + k]);
                }
            }
            float bi = __ldg(gru_bih + 128 + tt), bh = __ldg(gru_bhh + 128 + tt);
            #pragma unroll
            for (int r = 0; r < 4; ++r) nn[r] = tanhf(ai[r] + bi + rr[r] * (ah[r] + bh));
        }
        #pragma unroll
        for (int r = 0; r < 4; ++r) {
            int i = r0 + r;
            HN[i * 64 + tt] = (1.f - zz[r]) * nn[r] + zz[r] * SL[i * 64 + tt];
        }
    }
    __syncthreads();
    // LN stats (2-stage deterministic)
    {
        int ir = t >> 4, d0 = t & 15;
        float s1 = 0.f, s2 = 0.f;
        #pragma unroll
        for (int k = 0; k < 4; ++k) { float v = HN[ir * 64 + d0 + 16 * k]; s1 += v; s2 += v * v; }
        RD1[t] = s1; RD2[t] = s2;
    }
    __syncthreads();
    if (t < 8) {
        float s1 = 0.f, s2 = 0.f;
        #pragma unroll
        for (int q = 0; q < 16; ++q) { s1 += RD1[t * 16 + q]; s2 += RD2[t * 16 + q]; }
        float m = s1 * (1.f / 64.f);
        float var = s2 * (1.f / 64.f) - m * m;
        MM[t] = m; RS[t] = rsqrtf(var + 1e-5f);
    }
    __syncthreads();
    {
        float gg = npf_g[tt], bb = npf_b[tt];
        #pragma unroll
        for (int r = 0; r < 4; ++r) {
            int i = r0 + r;
            LNX[i * 64 + tt] = (HN[i * 64 + tt] - MM[i]) * RS[i] * gg + bb;
        }
    }
    __syncthreads();
    // MLP hidden (od = t)
    {
        float acc[8] = {0,0,0,0,0,0,0,0};
        const float4* w4 = (const float4*)(mlp_W1 + t * 64);
        const float4* l4 = (const float4*)LNX;
        #pragma unroll 4
        for (int k = 0; k < 16; ++k) {
            float4 w = __ldg(w4 + k);
            #pragma unroll
            for (int i = 0; i < 8; ++i) acc[i] += dot4(w, l4[i * 16 + k]);
        }
        float b1 = __ldg(mlp_b1 + t);
        #pragma unroll
        for (int i = 0; i < 8; ++i) B1[i * 128 + t] = fmaxf(acc[i] + b1, 0.f);
    }
    __syncthreads();
    // MLP out + residual -> SLN
    {
        float acc[4] = {0,0,0,0};
        const float4* w4 = (const float4*)(mlp_W2 + tt * 128);
        const float4* h4 = (const float4*)B1;
        #pragma unroll 4
        for (int k = 0; k < 32; ++k) {
            float4 w = __ldg(w4 + k);
            #pragma unroll
            for (int r = 0; r < 4; ++r) acc[r] += dot4(w, h4[(r0 + r) * 32 + k]);
        }
        float bb = __ldg(mlp_b2 + tt);
        #pragma unroll
        for (int r = 0; r < 4; ++r) {
            int i = r0 + r;
            float v = HN[i * 64 + tt] + acc[r] + bb;
            SLN[i * 64 + tt] = v;
            g_slots[(long)b * 512 + i * 64 + tt] = v;
            if (final_iter) out[(long)b * 512 + i * 64 + tt] = v;
        }
    }
    __syncthreads();
    // posterior hidden (od = t)
    {
        float acc[8] = {0,0,0,0,0,0,0,0};
        const float4* w4 = (const float4*)(sr_W1 + t * 64);
        const float4* s4 = (const float4*)SLN;
        #pragma unroll 4
        for (int k = 0; k < 16; ++k) {
            float4 w = __ldg(w4 + k);
            #pragma unroll
            for (int i = 0; i < 8; ++i) acc[i] += dot4(w, s4[i * 16 + k]);
        }
        float b1 = __ldg(sr_b1 + t);
        #pragma unroll
        for (int i = 0; i < 8; ++i) B1[i * 128 + t] = fmaxf(acc[i] + b1, 0.f);
    }
    __syncthreads();
    // posterior out -> B2
    {
        float acc[8] = {0,0,0,0,0,0,0,0};
        const float4* w4 = (const float4*)(sr_W2 + t * 128);
        const float4* h4 = (const float4*)B1;
        #pragma unroll 4
        for (int k = 0; k < 32; ++k) {
            float4 w = __ldg(w4 + k);
            #pragma unroll
            for (int i = 0; i < 8; ++i) acc[i] += dot4(w, h4[i * 32 + k]);
        }
        float b2 = __ldg(sr_b2 + t);
        #pragma unroll
        for (int i = 0; i < 8; ++i) B2[i * 128 + t] = acc[i] + b2;
    }
    __syncthreads();
    // KL terms -> U scratch, then 2-stage reduce
    if (t < 64) {
        #pragma unroll
        for (int i = 0; i < 8; ++i) {
            float po_m  = B2[i * 128 + t], po_lv = B2[i * 128 + 64 + t];
            float m_pr  = g_prior[(long)b * 1024 + i * 128 + t];
            float lv_pr = g_prior[(long)b * 1024 + i * 128 + 64 + t];
            float dm = po_m - m_pr;
            U[i * 64 + t] = lv_pr - po_lv + (expf(po_lv) + dm * dm) * expf(-lv_pr) - 1.0f;
        }
    }
    __syncthreads();
    {
        int ir = t >> 4, d0 = t & 15;
        float s1 = 0.f;
        #pragma unroll
        for (int k = 0; k < 4; ++k) s1 += U[ir * 64 + d0 + 16 * k];
        RD1[t] = s1;
    }
    __syncthreads();
    if (t < 8) {
        float s = 0.f;
        #pragma unroll
        for (int q = 0; q < 16; ++q) s += RD1[t * 16 + q];
        float v = g_kl[b * 8 + t] + 0.5f * s;
        g_kl[b * 8 + t] = v;
        if (final_iter) out[131072 + b * 8 + t] = v;
    }
    if (!final_iter) {
        __syncthreads();
        // q projection for next iteration
        {
            float acc[4] = {0,0,0,0};
            const float4* w4 = (const float4*)(Wq + tt * 64);
            const float4* s4 = (const float4*)SLN;
            #pragma unroll 4
            for (int k = 0; k < 16; ++k) {
                float4 w = __ldg(w4 + k);
                #pragma unroll
                for (int r = 0; r < 4; ++r) acc[r] += dot4(w, s4[(r0 + r) * 16 + k]);
            }
            float bb = __ldg(bq + tt);
            #pragma unroll
            for (int r = 0; r < 4; ++r) QT[(r0 + r) * 64 + tt] = acc[r] + bb;
        }
        __syncthreads();
        {
            float qp[4] = {0,0,0,0};
            for (int o = 0; o < 64; ++o) {
                float w = __ldg(Wk + o * 64 + tt);
                #pragma unroll
                for (int r = 0; r < 4; ++r) qp[r] += QT[(r0 + r) * 64 + o] * w;
            }
            float gg = ni_g[tt], nb = ni_b[tt], bkt = bk[tt];
            #pragma unroll
            for (int r = 0; r < 4; ++r) {
                int i = r0 + r;
                float q = qp[r] * SCALEF;
                float qgv = q * gg;
                g_qg[(long)b * 512 + i * 64 + tt] = qgv;
                B1[i * 64 + tt] = qgv;
                B1[512 + i * 64 + tt] = q * nb + SCALEF * QT[i * 64 + tt] * bkt;
            }
        }
        __syncthreads();
        {
            int ir = t >> 4, d0 = t & 15;
            float s1 = 0.f, s2 = 0.f;
            #pragma unroll
            for (int k = 0; k < 4; ++k) {
                s1 += B1[ir * 64 + d0 + 16 * k];
                s2 += B1[512 + ir * 64 + d0 + 16 * k];
            }
            RD1[t] = s1; RD2[t] = s2;
        }
        __syncthreads();
        if (t < 8) {
            float s1 = 0.f, s2 = 0.f;
            #pragma unroll
            for (int q = 0; q < 16; ++q) { s1 += RD1[t * 16 + q]; s2 += RD2[t * 16 + q]; }
            g_qgs[b * 8 + t] = s1;
            g_qb[b * 8 + t]  = s2;
        }
    }
}

// =======================================================================
extern "C" void kernel_launch(void* const* d_in, const int* in_sizes, int n_in,
                              void* d_out, int out_size)
{
    const float* inputs      = (const float*)d_in[0];
    const float* slots       = (const float*)d_in[1];
    const float* prior_slots = (const float*)d_in[2];
    const float* eps_noise   = (const float*)d_in[3];
    const float* ni_g  = (const float*)d_in[4];
    const float* ni_b  = (const float*)d_in[5];
    const float* npf_g = (const float*)d_in[6];
    const float* npf_b = (const float*)d_in[7];
    const float* Wq = (const float*)d_in[8];
    const float* bq = (const float*)d_in[9];
    const float* Wk = (const float*)d_in[10];
    const float* bk = (const float*)d_in[11];
    const float* Wv = (const float*)d_in[12];
    const float* bv = (const float*)d_in[13];
    const float* sr_W1 = (const float*)d_in[14];
    const float* sr_b1 = (const float*)d_in[15];
    const float* sr_W2 = (const float*)d_in[16];
    const float* sr_b2 = (const float*)d_in[17];
    const float* pr_W1 = (const float*)d_in[18];
    const float* pr_b1 = (const float*)d_in[19];
    const float* pr_W2 = (const float*)d_in[20];
    const float* pr_b2 = (const float*)d_in[21];
    const float* gru_Wih = (const float*)d_in[22];
    const float* gru_Whh = (const float*)d_in[23];
    const float* gru_bih = (const float*)d_in[24];
    const float* gru_bhh = (const float*)d_in[25];
    const float* mlp_W1 = (const float*)d_in[26];
    const float* mlp_b1 = (const float*)d_in[27];
    const float* mlp_W2 = (const float*)d_in[28];
    const float* mlp_b2 = (const float*)d_in[29];

    cudaFuncSetAttribute(attn_kernel, cudaFuncAttributeMaxDynamicSharedMemorySize, AQ_BYTES);

    init_kernel<<<NBATCH, 128>>>(slots, prior_slots, eps_noise,
                                 ni_g, ni_b,
                                 sr_W1, sr_b1, sr_W2, sr_b2,
                                 pr_W1, pr_b1, pr_W2, pr_b2,
                                 Wq, bq, Wk, bk);
    for (int it = 0; it < 3; ++it) {
        attn_kernel<<<NBATCH * NCH, 256, AQ_BYTES>>>(inputs);
        update_kernel<<<NBATCH, 128>>>(Wv, bv,
                                       gru_Wih, gru_Whh, gru_bih, gru_bhh,
                                       npf_g, npf_b,
                                       mlp_W1, mlp_b1, mlp_W2, mlp_b2,
                                       sr_W1, sr_b1, sr_W2, sr_b2,
                                       ni_g, ni_b, Wq, bq, Wk, bk,
                                       it == 2 ? 1 : 0, (float*)d_out);
    }
}

// round 15
// speedup vs baseline: 7.9904x; 1.3102x over previous
#include <cuda_runtime.h>

#define NBATCH 256
#define NTOK   4096
#define NCH    16
#define SCALEF 0.125f
#define EPSA   1e-8f

// ---------------- global scratch ----------------
__device__ float g_slots[NBATCH * 512];
__device__ float g_prior[NBATCH * 1024];
__device__ float g_kl[NBATCH * 8];
__device__ float g_qg[NBATCH * 512];
__device__ float g_qgs[NBATCH * 8];
__device__ float g_qb[NBATCH * 8];
__device__ float g_pA[NBATCH * NCH * 8 * 64];
__device__ float g_pW[NBATCH * NCH * 8];
__device__ float g_pT[NBATCH * NCH * 8];

__device__ __forceinline__ float sigmoidf_(float x) { return 1.0f / (1.0f + expf(-x)); }
__device__ __forceinline__ float dot4(float4 a, float4 b) {
    return a.x * b.x + a.y * b.y + a.z * b.z + a.w * b.w;
}

// ---- TMA bulk 1D helpers ----
__device__ __forceinline__ void mbar_init(unsigned mbar, unsigned count) {
    asm volatile("mbarrier.init.shared.b64 [%0], %1;" :: "r"(mbar), "r"(count) : "memory");
}
__device__ __forceinline__ void mbar_expect_tx(unsigned mbar, unsigned bytes) {
    asm volatile("mbarrier.arrive.expect_tx.shared.b64 _, [%0], %1;" :: "r"(mbar), "r"(bytes) : "memory");
}
__device__ __forceinline__ void tma_bulk_g2s(unsigned smem_dst, const void* gsrc, unsigned bytes, unsigned mbar) {
    asm volatile(
        "cp.async.bulk.shared::cta.global.mbarrier::complete_tx::bytes [%0], [%1], %2, [%3];"
        :: "r"(smem_dst), "l"(gsrc), "r"(bytes), "r"(mbar) : "memory");
}
__device__ __forceinline__ void mbar_wait(unsigned mbar, unsigned phase) {
    asm volatile(
        "{\n\t"
        ".reg .pred P;\n\t"
        "WAITLOOP_%=:\n\t"
        "mbarrier.try_wait.parity.shared.b64 P, [%0], %1;\n\t"
        "@!P bra WAITLOOP_%=;\n\t"
        "}"
        :: "r"(mbar), "r"(phase) : "memory");
}

// =======================================================================
// ATTENTION: 4096 blocks (batch x 16 chunks of 256 tokens) x 256 threads
// TMA bulk double-buffered tiles, unpadded [64][64] layout.
// =======================================================================
#define AQ_QG   0           // [8][68] padded (17 float4 per slot)
#define AQ_QGS  544
#define AQ_QB   552
#define AQ_MB   560         // 2 mbarriers (2 x u64 = 4 floats)
#define AQ_WT2  564         // [64 tokens][8 slots] w'
#define AQ_WR   1076        // [64][8]
#define AQ_TR   1588        // [64][8]
#define AQ_KT0  2112        // [64][64] floats, 128B-aligned (2112*4 % 128 == 0)
#define AQ_KT1  6208        // 6208*4 % 128 == 0
#define AQ_RED  AQ_KT0      // epilogue alias (last tile uses KT1)
#define AQ_TOT  10304
#define AQ_BYTES (AQ_TOT * 4)
#define TILE_BYTES 16384u

__global__ __launch_bounds__(256, 4) void attn_kernel(const float* __restrict__ inputs)
{
    extern __shared__ float sm[];
    const int blk = blockIdx.x;
    const int b = blk >> 4, chunk = blk & 15;
    const int t = threadIdx.x;
    const unsigned smem_base = (unsigned)__cvta_generic_to_shared(sm);
    const unsigned mb0 = smem_base + AQ_MB * 4;
    const unsigned mb1 = mb0 + 8;

    for (int e = t; e < 512; e += 256)
        sm[AQ_QG + (e >> 6) * 68 + (e & 63)] = g_qg[b * 512 + e];
    if (t < 8) { sm[AQ_QGS + t] = g_qgs[b * 8 + t]; sm[AQ_QB + t] = g_qb[b * 8 + t]; }

    const float* base = inputs + ((long)b * NTOK + chunk * 256) * 64;

    if (t == 0) {
        mbar_init(mb0, 1);
        mbar_init(mb1, 1);
    }
    __syncthreads();
    asm volatile("fence.proxy.async.shared::cta;" ::: "memory");
    if (t == 0) {
        mbar_expect_tx(mb0, TILE_BYTES);
        tma_bulk_g2s(smem_base + AQ_KT0 * 4, base, TILE_BYTES, mb0);
        mbar_expect_tx(mb1, TILE_BYTES);
        tma_bulk_g2s(smem_base + AQ_KT1 * 4, base + 64 * 64, TILE_BYTES, mb1);
    }

    // dots roles
    const int j = t >> 2, seg = t & 3;
    const int i0 = seg * 2;
    const int rot = (2 * (j & 1) + (seg >> 1)) & 3;   // bank-conflict-free rotation
    // accum roles
    const int a_d8 = t & 7, a_p = (t >> 3) & 3, a_jg = t >> 5;
    float4 a00 = {0,0,0,0}, a01 = {0,0,0,0}, a10 = {0,0,0,0}, a11 = {0,0,0,0};
    float Wp0 = 0.f, Wp1 = 0.f, Tp0 = 0.f, Tp1 = 0.f;

    for (int tt = 0; tt < 4; ++tt) {
        const int buf = tt & 1;
        float4* kt4 = (float4*)(sm + (buf ? AQ_KT1 : AQ_KT0));
        mbar_wait(buf ? mb1 : mb0, (tt >> 1) & 1);
        __syncthreads();

        // ---- dots (LN folded), rotated c for conflict-free unpadded reads ----
        {
            float s = 0.f, ss = 0.f;
            float dp[8];
            #pragma unroll
            for (int i = 0; i < 8; ++i) dp[i] = 0.f;
            const float4* xrow = kt4 + j * 16 + seg * 4;
            const float4* qg4  = (const float4*)(sm + AQ_QG);
            #pragma unroll
            for (int c = 0; c < 4; ++c) {
                int cc = (c + rot) & 3;
                float4 x4 = xrow[cc];
                s  += (x4.x + x4.y) + (x4.z + x4.w);
                ss += x4.x * x4.x + x4.y * x4.y + x4.z * x4.z + x4.w * x4.w;
                #pragma unroll
                for (int i = 0; i < 8; ++i)
                    dp[i] += dot4(x4, qg4[i * 17 + seg * 4 + cc]);
            }
            s  += __shfl_xor_sync(~0u, s, 1);  s  += __shfl_xor_sync(~0u, s, 2);
            ss += __shfl_xor_sync(~0u, ss, 1); ss += __shfl_xor_sync(~0u, ss, 2);
            #pragma unroll
            for (int i = 0; i < 8; ++i) {
                dp[i] += __shfl_xor_sync(~0u, dp[i], 1);
                dp[i] += __shfl_xor_sync(~0u, dp[i], 2);
            }
            float m = s * (1.f / 64.f);
            float var = ss * (1.f / 64.f) - m * m;
            float rstd = rsqrtf(var + 1e-5f);
            float mr = m * rstd;
            float dv0 = rstd * dp[i0]     - mr * sm[AQ_QGS + i0]     + sm[AQ_QB + i0];
            float dv1 = rstd * dp[i0 + 1] - mr * sm[AQ_QGS + i0 + 1] + sm[AQ_QB + i0 + 1];
            float mx = fmaxf(dv0, dv1);
            mx = fmaxf(mx, __shfl_xor_sync(~0u, mx, 1));
            mx = fmaxf(mx, __shfl_xor_sync(~0u, mx, 2));
            float e0 = __expf(dv0 - mx), e1 = __expf(dv1 - mx);
            float sum = e0 + e1;
            sum += __shfl_xor_sync(~0u, sum, 1);
            sum += __shfl_xor_sync(~0u, sum, 2);
            float inv = 1.0f / sum;
            float w0 = e0 * inv + EPSA, w1 = e1 * inv + EPSA;
            float wp0 = w0 * rstd, wp1 = w1 * rstd;
            ((float2*)(sm + AQ_WT2))[j * 4 + seg] = make_float2(wp0, wp1);
            Wp0 += w0; Wp1 += w1;
            Tp0 += wp0 * m; Tp1 += wp1 * m;
        }
        __syncthreads();

        // ---- accumulate: 2 slots per thread (conflict-free unpadded) ----
        #pragma unroll
        for (int k = 0; k < 8; ++k) {
            int jj = a_jg * 8 + k;
            float2 wp = ((float2*)(sm + AQ_WT2))[jj * 4 + a_p];
            float4 x0 = kt4[jj * 16 + a_d8];
            float4 x1 = kt4[jj * 16 + a_d8 + 8];
            a00.x += wp.x * x0.x; a00.y += wp.x * x0.y; a00.z += wp.x * x0.z; a00.w += wp.x * x0.w;
            a01.x += wp.x * x1.x; a01.y += wp.x * x1.y; a01.z += wp.x * x1.z; a01.w += wp.x * x1.w;
            a10.x += wp.y * x0.x; a10.y += wp.y * x0.y; a10.z += wp.y * x0.z; a10.w += wp.y * x0.w;
            a11.x += wp.y * x1.x; a11.y += wp.y * x1.y; a11.z += wp.y * x1.z; a11.w += wp.y * x1.w;
        }
        __syncthreads();

        // ---- refill this buffer with tile tt+2 (all reads of it are done) ----
        if (tt < 2 && t == 0) {
            unsigned mb = buf ? mb1 : mb0;
            mbar_expect_tx(mb, TILE_BYTES);
            tma_bulk_g2s(smem_base + (buf ? AQ_KT1 : AQ_KT0) * 4,
                         base + (unsigned)(tt + 2) * 64 * 64, TILE_BYTES, mb);
        }
    }

    // ---- epilogue (RED aliases KT0; last tile used KT1) ----
    {
        float4* red = (float4*)(sm + AQ_RED);
        red[t * 4 + 0] = a00; red[t * 4 + 1] = a01;
        red[t * 4 + 2] = a10; red[t * 4 + 3] = a11;
        sm[AQ_WR + j * 8 + i0]     = Wp0;
        sm[AQ_WR + j * 8 + i0 + 1] = Wp1;
        sm[AQ_TR + j * 8 + i0]     = Tp0;
        sm[AQ_TR + j * 8 + i0 + 1] = Tp1;
    }
    __syncthreads();
    for (int e = t; e < 512; e += 256) {
        int i = e >> 6, d = e & 63;
        int pair = i >> 1, comp = i & 1, half = d >> 5, d8 = (d & 31) >> 2, elem = d & 3;
        int c = comp * 2 + half;
        float A = 0.f;
        #pragma unroll
        for (int jg = 0; jg < 8; ++jg) {
            int tp = jg * 32 + pair * 8 + d8;
            A += sm[AQ_RED + tp * 16 + c * 4 + elem];
        }
        g_pA[((b * NCH + chunk) * 8 + i) * 64 + d] = A;
    }
    if (t < 8) {
        float w = 0.f, ti = 0.f;
        #pragma unroll 8
        for (int jj = 0; jj < 64; ++jj) { w += sm[AQ_WR + jj * 8 + t]; ti += sm[AQ_TR + jj * 8 + t]; }
        g_pW[(b * NCH + chunk) * 8 + t] = w;
        g_pT[(b * NCH + chunk) * 8 + t] = ti;
    }
}

// =======================================================================
// INIT: 256 blocks (batch) x 128 threads, weights streamed once per block
// =======================================================================
__global__ __launch_bounds__(128) void init_kernel(
    const float* __restrict__ slots_in, const float* __restrict__ prior_slots,
    const float* __restrict__ eps_noise,
    const float* __restrict__ ni_g, const float* __restrict__ ni_b,
    const float* __restrict__ sr_W1, const float* __restrict__ sr_b1,
    const float* __restrict__ sr_W2, const float* __restrict__ sr_b2,
    const float* __restrict__ pr_W1, const float* __restrict__ pr_b1,
    const float* __restrict__ pr_W2, const float* __restrict__ pr_b2,
    const float* __restrict__ Wq, const float* __restrict__ bq,
    const float* __restrict__ Wk, const float* __restrict__ bk)
{
    __shared__ float P0[512], S0[512], B1[1024], B2[1024], SLN[512], QT[512];
    __shared__ float RD1[128], RD2[128];
    const int b = blockIdx.x, t = threadIdx.x;
    const int tt = t & 63, r0 = (t >> 6) * 4;

    for (int e = t; e < 512; e += 128) {
        P0[e] = prior_slots[(long)b * 512 + e];
        S0[e] = slots_in[(long)b * 512 + e];
    }
    if (t < 8) g_kl[b * 8 + t] = 0.f;
    __syncthreads();
    {
        float acc[8] = {0,0,0,0,0,0,0,0};
        const float4* w4 = (const float4*)(pr_W1 + t * 64);
        const float4* p4 = (const float4*)P0;
        #pragma unroll 4
        for (int k = 0; k < 16; ++k) {
            float4 w = __ldg(w4 + k);
            #pragma unroll
            for (int i = 0; i < 8; ++i) acc[i] += dot4(w, p4[i * 16 + k]);
        }
        float b1 = __ldg(pr_b1 + t);
        #pragma unroll
        for (int i = 0; i < 8; ++i) B1[i * 128 + t] = fmaxf(acc[i] + b1, 0.f);
    }
    __syncthreads();
    {
        float acc[8] = {0,0,0,0,0,0,0,0};
        const float4* w4 = (const float4*)(pr_W2 + t * 128);
        const float4* h4 = (const float4*)B1;
        #pragma unroll 4
        for (int k = 0; k < 32; ++k) {
            float4 w = __ldg(w4 + k);
            #pragma unroll
            for (int i = 0; i < 8; ++i) acc[i] += dot4(w, h4[i * 32 + k]);
        }
        float b2 = __ldg(pr_b2 + t);
        #pragma unroll
        for (int i = 0; i < 8; ++i) g_prior[(long)b * 1024 + i * 128 + t] = acc[i] + b2;
    }
    __syncthreads();
    {
        float acc[8] = {0,0,0,0,0,0,0,0};
        const float4* w4 = (const float4*)(sr_W1 + t * 64);
        const float4* s4 = (const float4*)S0;
        #pragma unroll 4
        for (int k = 0; k < 16; ++k) {
            float4 w = __ldg(w4 + k);
            #pragma unroll
            for (int i = 0; i < 8; ++i) acc[i] += dot4(w, s4[i * 16 + k]);
        }
        float b1 = __ldg(sr_b1 + t);
        #pragma unroll
        for (int i = 0; i < 8; ++i) B1[i * 128 + t] = fmaxf(acc[i] + b1, 0.f);
    }
    __syncthreads();
    {
        float acc[8] = {0,0,0,0,0,0,0,0};
        const float4* w4 = (const float4*)(sr_W2 + t * 128);
        const float4* h4 = (const float4*)B1;
        #pragma unroll 4
        for (int k = 0; k < 32; ++k) {
            float4 w = __ldg(w4 + k);
            #pragma unroll
            for (int i = 0; i < 8; ++i) acc[i] += dot4(w, h4[i * 32 + k]);
        }
        float b2 = __ldg(sr_b2 + t);
        #pragma unroll
        for (int i = 0; i < 8; ++i) B2[i * 128 + t] = acc[i] + b2;
    }
    __syncthreads();
    for (int e = t; e < 512; e += 128) {
        int i = e >> 6, d = e & 63;
        float mu = B2[i * 128 + d], lv = B2[i * 128 + 64 + d];
        float v = eps_noise[(long)b * 512 + e] * expf(0.5f * lv) + mu;
        SLN[e] = v;
        g_slots[(long)b * 512 + e] = v;
    }
    __syncthreads();
    {
        float acc[4] = {0,0,0,0};
        const float4* w4 = (const float4*)(Wq + tt * 64);
        const float4* s4 = (const float4*)SLN;
        #pragma unroll 4
        for (int k = 0; k < 16; ++k) {
            float4 w = __ldg(w4 + k);
            #pragma unroll
            for (int r = 0; r < 4; ++r) acc[r] += dot4(w, s4[(r0 + r) * 16 + k]);
        }
        float bb = __ldg(bq + tt);
        #pragma unroll
        for (int r = 0; r < 4; ++r) QT[(r0 + r) * 64 + tt] = acc[r] + bb;
    }
    __syncthreads();
    {
        float qp[4] = {0,0,0,0};
        for (int o = 0; o < 64; ++o) {
            float w = __ldg(Wk + o * 64 + tt);
            #pragma unroll
            for (int r = 0; r < 4; ++r) qp[r] += QT[(r0 + r) * 64 + o] * w;
        }
        float gg = ni_g[tt], nb = ni_b[tt], bkt = bk[tt];
        #pragma unroll
        for (int r = 0; r < 4; ++r) {
            int i = r0 + r;
            float q = qp[r] * SCALEF;
            float qgv = q * gg;
            g_qg[(long)b * 512 + i * 64 + tt] = qgv;
            B1[i * 64 + tt] = qgv;
            B1[512 + i * 64 + tt] = q * nb + SCALEF * QT[i * 64 + tt] * bkt;
        }
    }
    __syncthreads();
    {
        int ir = t >> 4, d0 = t & 15;
        float s1 = 0.f, s2 = 0.f;
        #pragma unroll
        for (int k = 0; k < 4; ++k) {
            s1 += B1[ir * 64 + d0 + 16 * k];
            s2 += B1[512 + ir * 64 + d0 + 16 * k];
        }
        RD1[t] = s1; RD2[t] = s2;
    }
    __syncthreads();
    if (t < 8) {
        float s1 = 0.f, s2 = 0.f;
        #pragma unroll
        for (int q = 0; q < 16; ++q) { s1 += RD1[t * 16 + q]; s2 += RD2[t * 16 + q]; }
        g_qgs[b * 8 + t] = s1;
        g_qb[b * 8 + t]  = s2;
    }
}

// =======================================================================
// UPDATE: 256 blocks (batch) x 128 threads
// =======================================================================
__global__ __launch_bounds__(128) void update_kernel(
    const float* __restrict__ Wv, const float* __restrict__ bv,
    const float* __restrict__ gru_Wih, const float* __restrict__ gru_Whh,
    const float* __restrict__ gru_bih, const float* __restrict__ gru_bhh,
    const float* __restrict__ npf_g, const float* __restrict__ npf_b,
    const float* __restrict__ mlp_W1, const float* __restrict__ mlp_b1,
    const float* __restrict__ mlp_W2, const float* __restrict__ mlp_b2,
    const float* __restrict__ sr_W1, const float* __restrict__ sr_b1,
    const float* __restrict__ sr_W2, const float* __restrict__ sr_b2,
    const float* __restrict__ ni_g, const float* __restrict__ ni_b,
    const float* __restrict__ Wq, const float* __restrict__ bq,
    const float* __restrict__ Wk, const float* __restrict__ bk,
    int final_iter, float* __restrict__ out)
{
    __shared__ float SL[512], NUM[512], U[512], HN[512], LNX[512], SLN[512], QT[512];
    __shared__ float B1[1024], B2[1024];
    __shared__ float RD1[128], RD2[128], MM[8], RS[8], DINV[8], TI[8];
    const int b = blockIdx.x, t = threadIdx.x;
    const int tt = t & 63, r0 = (t >> 6) * 4;

    for (int e = t; e < 512; e += 128) SL[e] = g_slots[(long)b * 512 + e];
    if (t < 8) {
        float den = 0.f, ti = 0.f;
        #pragma unroll 4
        for (int c = 0; c < NCH; ++c) {
            den += g_pW[(b * NCH + c) * 8 + t];
            ti  += g_pT[(b * NCH + c) * 8 + t];
        }
        DINV[t] = 1.0f / den; TI[t] = ti;
    }
    __syncthreads();
    {
        float gg = ni_g[tt], bb = ni_b[tt];
        #pragma unroll
        for (int r = 0; r < 4; ++r) {
            int i = r0 + r;
            float A = 0.f;
            #pragma unroll 4
            for (int c = 0; c < NCH; ++c) A += g_pA[((b * NCH + c) * 8 + i) * 64 + tt];
            NUM[i * 64 + tt] = gg * (A - TI[i]) * DINV[i] + bb;
        }
    }
    __syncthreads();
    {
        float acc[4] = {0,0,0,0};
        const float4* w4 = (const float4*)(Wv + tt * 64);
        const float4* n4 = (const float4*)NUM;
        #pragma unroll 4
        for (int k = 0; k < 16; ++k) {
            float4 w = __ldg(w4 + k);
            #pragma unroll
            for (int r = 0; r < 4; ++r) acc[r] += dot4(w, n4[(r0 + r) * 16 + k]);
        }
        float bb = __ldg(bv + tt);
        #pragma unroll
        for (int r = 0; r < 4; ++r) U[(r0 + r) * 64 + tt] = acc[r] + bb;
    }
    __syncthreads();
    {
        const float4* u4 = (const float4*)U;
        const float4* s4 = (const float4*)SL;
        float rr[4], zz[4], nn[4];
        {
            float ai[4] = {0,0,0,0}, ah[4] = {0,0,0,0};
            const float4* wi = (const float4*)(gru_Wih + tt * 64);
            const float4* wh = (const float4*)(gru_Whh + tt * 64);
            #pragma unroll 4
            for (int k = 0; k < 16; ++k) {
                float4 a = __ldg(wi + k), h = __ldg(wh + k);
                #pragma unroll
                for (int r = 0; r < 4; ++r) {
                    ai[r] += dot4(a, u4[(r0 + r) * 16 + k]);
                    ah[r] += dot4(h, s4[(r0 + r) * 16 + k]);
                }
            }
            float bi = __ldg(gru_bih + tt), bh = __ldg(gru_bhh + tt);
            #pragma unroll
            for (int r = 0; r < 4; ++r) rr[r] = sigmoidf_(ai[r] + bi + ah[r] + bh);
        }
        {
            float ai[4] = {0,0,0,0}, ah[4] = {0,0,0,0};
            const float4* wi = (const float4*)(gru_Wih + (64 + tt) * 64);
            const float4* wh = (const float4*)(gru_Whh + (64 + tt) * 64);
            #pragma unroll 4
            for (int k = 0; k < 16; ++k) {
                float4 a = __ldg(wi + k), h = __ldg(wh + k);
                #pragma unroll
                for (int r = 0; r < 4; ++r) {
                    ai[r] += dot4(a, u4[(r0 + r) * 16 + k]);
                    ah[r] += dot4(h, s4[(r0 + r) * 16 + k]);
                }
            }
            float bi = __ldg(gru_bih + 64 + tt), bh = __ldg(gru_bhh + 64 + tt);
            #pragma unroll
            for (int r = 0; r < 4; ++r) zz[r] = sigmoidf_(ai[r] + bi + ah[r] + bh);
        }
        {
            float ai[4] = {0,0,0,0}, ah[4] = {0,0,0,0};
            const float4* wi = (const float4*)(gru_Wih + (128 + tt) * 64);
            const float4* wh = (const float4*)(gru_Whh + (128 + tt) * 64);
            #pragma unroll 4
            for (int k = 0; k < 16; ++k) {
                float4 a = __ldg(wi + k), h = __ldg(wh + k);
                #pragma unroll
                for (int r = 0; r < 4; ++r) {
                    ai[r] += dot4(a, u4[(r0 + r) * 16 + k]);
                    ah[r] += dot4(h, s4[(r0 + r) * 16 + k]);
                }
            }
            float bi = __ldg(gru_bih + 128 + tt), bh = __ldg(gru_bhh + 128 + tt);
            #pragma unroll
            for (int r = 0; r < 4; ++r) nn[r] = tanhf(ai[r] + bi + rr[r] * (ah[r] + bh));
        }
        #pragma unroll
        for (int r = 0; r < 4; ++r) {
            int i = r0 + r;
            HN[i * 64 + tt] = (1.f - zz[r]) * nn[r] + zz[r] * SL[i * 64 + tt];
        }
    }
    __syncthreads();
    {
        int ir = t >> 4, d0 = t & 15;
        float s1 = 0.f, s2 = 0.f;
        #pragma unroll
        for (int k = 0; k < 4; ++k) { float v = HN[ir * 64 + d0 + 16 * k]; s1 += v; s2 += v * v; }
        RD1[t] = s1; RD2[t] = s2;
    }
    __syncthreads();
    if (t < 8) {
        float s1 = 0.f, s2 = 0.f;
        #pragma unroll
        for (int q = 0; q < 16; ++q) { s1 += RD1[t * 16 + q]; s2 += RD2[t * 16 + q]; }
        float m = s1 * (1.f / 64.f);
        float var = s2 * (1.f / 64.f) - m * m;
        MM[t] = m; RS[t] = rsqrtf(var + 1e-5f);
    }
    __syncthreads();
    {
        float gg = npf_g[tt], bb = npf_b[tt];
        #pragma unroll
        for (int r = 0; r < 4; ++r) {
            int i = r0 + r;
            LNX[i * 64 + tt] = (HN[i * 64 + tt] - MM[i]) * RS[i] * gg + bb;
        }
    }
    __syncthreads();
    {
        float acc[8] = {0,0,0,0,0,0,0,0};
        const float4* w4 = (const float4*)(mlp_W1 + t * 64);
        const float4* l4 = (const float4*)LNX;
        #pragma unroll 4
        for (int k = 0; k < 16; ++k) {
            float4 w = __ldg(w4 + k);
            #pragma unroll
            for (int i = 0; i < 8; ++i) acc[i] += dot4(w, l4[i * 16 + k]);
        }
        float b1 = __ldg(mlp_b1 + t);
        #pragma unroll
        for (int i = 0; i < 8; ++i) B1[i * 128 + t] = fmaxf(acc[i] + b1, 0.f);
    }
    __syncthreads();
    {
        float acc[4] = {0,0,0,0};
        const float4* w4 = (const float4*)(mlp_W2 + tt * 128);
        const float4* h4 = (const float4*)B1;
        #pragma unroll 4
        for (int k = 0; k < 32; ++k) {
            float4 w = __ldg(w4 + k);
            #pragma unroll
            for (int r = 0; r < 4; ++r) acc[r] += dot4(w, h4[(r0 + r) * 32 + k]);
        }
        float bb = __ldg(mlp_b2 + tt);
        #pragma unroll
        for (int r = 0; r < 4; ++r) {
            int i = r0 + r;
            float v = HN[i * 64 + tt] + acc[r] + bb;
            SLN[i * 64 + tt] = v;
            g_slots[(long)b * 512 + i * 64 + tt] = v;
            if (final_iter) out[(long)b * 512 + i * 64 + tt] = v;
        }
    }
    __syncthreads();
    {
        float acc[8] = {0,0,0,0,0,0,0,0};
        const float4* w4 = (const float4*)(sr_W1 + t * 64);
        const float4* s4 = (const float4*)SLN;
        #pragma unroll 4
        for (int k = 0; k < 16; ++k) {
            float4 w = __ldg(w4 + k);
            #pragma unroll
            for (int i = 0; i < 8; ++i) acc[i] += dot4(w, s4[i * 16 + k]);
        }
        float b1 = __ldg(sr_b1 + t);
        #pragma unroll
        for (int i = 0; i < 8; ++i) B1[i * 128 + t] = fmaxf(acc[i] + b1, 0.f);
    }
    __syncthreads();
    {
        float acc[8] = {0,0,0,0,0,0,0,0};
        const float4* w4 = (const float4*)(sr_W2 + t * 128);
        const float4* h4 = (const float4*)B1;
        #pragma unroll 4
        for (int k = 0; k < 32; ++k) {
            float4 w = __ldg(w4 + k);
            #pragma unroll
            for (int i = 0; i < 8; ++i) acc[i] += dot4(w, h4[i * 32 + k]);
        }
        float b2 = __ldg(sr_b2 + t);
        #pragma unroll
        for (int i = 0; i < 8; ++i) B2[i * 128 + t] = acc[i] + b2;
    }
    __syncthreads();
    if (t < 64) {
        #pragma unroll
        for (int i = 0; i < 8; ++i) {
            float po_m  = B2[i * 128 + t], po_lv = B2[i * 128 + 64 + t];
            float m_pr  = g_prior[(long)b * 1024 + i * 128 + t];
            float lv_pr = g_prior[(long)b * 1024 + i * 128 + 64 + t];
            float dm = po_m - m_pr;
            U[i * 64 + t] = lv_pr - po_lv + (expf(po_lv) + dm * dm) * expf(-lv_pr) - 1.0f;
        }
    }
    __syncthreads();
    {
        int ir = t >> 4, d0 = t & 15;
        float s1 = 0.f;
        #pragma unroll
        for (int k = 0; k < 4; ++k) s1 += U[ir * 64 + d0 + 16 * k];
        RD1[t] = s1;
    }
    __syncthreads();
    if (t < 8) {
        float s = 0.f;
        #pragma unroll
        for (int q = 0; q < 16; ++q) s += RD1[t * 16 + q];
        float v = g_kl[b * 8 + t] + 0.5f * s;
        g_kl[b * 8 + t] = v;
        if (final_iter) out[131072 + b * 8 + t] = v;
    }
    if (!final_iter) {
        __syncthreads();
        {
            float acc[4] = {0,0,0,0};
            const float4* w4 = (const float4*)(Wq + tt * 64);
            const float4* s4 = (const float4*)SLN;
            #pragma unroll 4
            for (int k = 0; k < 16; ++k) {
                float4 w = __ldg(w4 + k);
                #pragma unroll
                for (int r = 0; r < 4; ++r) acc[r] += dot4(w, s4[(r0 + r) * 16 + k]);
            }
            float bb = __ldg(bq + tt);
            #pragma unroll
            for (int r = 0; r < 4; ++r) QT[(r0 + r) * 64 + tt] = acc[r] + bb;
        }
        __syncthreads();
        {
            float qp[4] = {0,0,0,0};
            for (int o = 0; o < 64; ++o) {
                float w = __ldg(Wk + o * 64 + tt);
                #pragma unroll
                for (int r = 0; r < 4; ++r) qp[r] += QT[(r0 + r) * 64 + o] * w;
            }
            float gg = ni_g[tt], nb = ni_b[tt], bkt = bk[tt];
            #pragma unroll
            for (int r = 0; r < 4; ++r) {
                int i = r0 + r;
                float q = qp[r] * SCALEF;
                float qgv = q * gg;
                g_qg[(long)b * 512 + i * 64 + tt] = qgv;
                B1[i * 64 + tt] = qgv;
                B1[512 + i * 64 + tt] = q * nb + SCALEF * QT[i * 64 + tt] * bkt;
            }
        }
        __syncthreads();
        {
            int ir = t >> 4, d0 = t & 15;
            float s1 = 0.f, s2 = 0.f;
            #pragma unroll
            for (int k = 0; k < 4; ++k) {
                s1 += B1[ir * 64 + d0 + 16 * k];
                s2 += B1[512 + ir * 64 + d0 + 16 * k];
            }
            RD1[t] = s1; RD2[t] = s2;
        }
        __syncthreads();
        if (t < 8) {
            float s1 = 0.f, s2 = 0.f;
            #pragma unroll
            for (int q = 0; q < 16; ++q) { s1 += RD1[t * 16 + q]; s2 += RD2[t * 16 + q]; }
            g_qgs[b * 8 + t] = s1;
            g_qb[b * 8 + t]  = s2;
        }
    }
}

// =======================================================================
extern "C" void kernel_launch(void* const* d_in, const int* in_sizes, int n_in,
                              void* d_out, int out_size)
{
    const float* inputs      = (const float*)d_in[0];
    const float* slots       = (const float*)d_in[1];
    const float* prior_slots = (const float*)d_in[2];
    const float* eps_noise   = (const float*)d_in[3];
    const float* ni_g  = (const float*)d_in[4];
    const float* ni_b  = (const float*)d_in[5];
    const float* npf_g = (const float*)d_in[6];
    const float* npf_b = (const float*)d_in[7];
    const float* Wq = (const float*)d_in[8];
    const float* bq = (const float*)d_in[9];
    const float* Wk = (const float*)d_in[10];
    const float* bk = (const float*)d_in[11];
    const float* Wv = (const float*)d_in[12];
    const float* bv = (const float*)d_in[13];
    const float* sr_W1 = (const float*)d_in[14];
    const float* sr_b1 = (const float*)d_in[15];
    const float* sr_W2 = (const float*)d_in[16];
    const float* sr_b2 = (const float*)d_in[17];
    const float* pr_W1 = (const float*)d_in[18];
    const float* pr_b1 = (const float*)d_in[19];
    const float* pr_W2 = (const float*)d_in[20];
    const float* pr_b2 = (const float*)d_in[21];
    const float* gru_Wih = (const float*)d_in[22];
    const float* gru_Whh = (const float*)d_in[23];
    const float* gru_bih = (const float*)d_in[24];
    const float* gru_bhh = (const float*)d_in[25];
    const float* mlp_W1 = (const float*)d_in[26];
    const float* mlp_b1 = (const float*)d_in[27];
    const float* mlp_W2 = (const float*)d_in[28];
    const float* mlp_b2 = (const float*)d_in[29];

    cudaFuncSetAttribute(attn_kernel, cudaFuncAttributeMaxDynamicSharedMemorySize, AQ_BYTES);

    init_kernel<<<NBATCH, 128>>>(slots, prior_slots, eps_noise,
                                 ni_g, ni_b,
                                 sr_W1, sr_b1, sr_W2, sr_b2,
                                 pr_W1, pr_b1, pr_W2, pr_b2,
                                 Wq, bq, Wk, bk);
    for (int it = 0; it < 3; ++it) {
        attn_kernel<<<NBATCH * NCH, 256, AQ_BYTES>>>(inputs);
        update_kernel<<<NBATCH, 128>>>(Wv, bv,
                                       gru_Wih, gru_Whh, gru_bih, gru_bhh,
                                       npf_g, npf_b,
                                       mlp_W1, mlp_b1, mlp_W2, mlp_b2,
                                       sr_W1, sr_b1, sr_W2, sr_b2,
                                       ni_g, ni_b, Wq, bq, Wk, bk,
                                       it == 2 ? 1 : 0, (float*)d_out);
    }
}